// round 1
// baseline (speedup 1.0000x reference)
#include <cuda_runtime.h>
#include <cuda_bf16.h>
#include <math.h>

// ---------------- problem constants ----------------
#define S_      2048
#define HID_    2048
#define H_      16
#define D_NOPE  128
#define D_ROPE  64
#define D_V     128
#define QHEAD   192      // D_NOPE + D_ROPE
#define QL_     1536
#define KVL_    512
#define CKV_W   576      // KVL + D_ROPE
#define QDIM    3072     // H*QHEAD
#define KVDIM   4096     // H*(D_NOPE+D_V)
#define EPS_    1e-6f
#define SCALE_  0.07216878364870322f  // 192^-0.5

// ---------------- scratch (device globals; no allocs allowed) ----------------
__device__ float g_qa    [S_ * QL_];
__device__ float g_qn    [S_ * QL_];
__device__ float g_ckv   [S_ * CKV_W];
__device__ float g_cnorm [S_ * KVL_];
__device__ float g_kpe   [S_ * D_ROPE];
__device__ float g_q     [S_ * QDIM];
__device__ float g_kv    [S_ * KVDIM];
__device__ float g_Q     [H_ * S_ * QHEAD];
__device__ float g_K     [H_ * S_ * QHEAD];
__device__ float g_V     [H_ * S_ * D_V];
__device__ float g_scores[(size_t)H_ * S_ * S_];   // 256 MB
__device__ float g_attn  [S_ * (H_ * D_V)];

// ---------------- generic tiled SGEMM ----------------
// C[M,N] = A[M,K] * B  (B row-major [K,N] if !TRANSB, else [N,K] and we use B^T)
// causal_mode: 0 none; 1 skip blocks fully above diagonal (M==N score tiles);
//              2 limit K-loop to row0+BM (PV: P is exactly 0 past the causal frontier)
#define BM 128
#define BN 128
#define BKK 8
#define TM 8
#define TN 8

template<bool TRANSB>
__global__ __launch_bounds__(256)
void sgemm_kernel(const float* __restrict__ A, int lda, size_t sA,
                  const float* __restrict__ B, int ldb, size_t sB,
                  float* __restrict__ C, int ldc, size_t sC,
                  int M, int N, int K, int causal_mode)
{
    int bz = blockIdx.z;
    A += (size_t)bz * sA;  B += (size_t)bz * sB;  C += (size_t)bz * sC;

    const int row0 = blockIdx.y * BM;
    const int col0 = blockIdx.x * BN;
    if (causal_mode == 1 && col0 > row0 + BM - 1) return;  // fully masked tile
    int Keff = (causal_mode == 2) ? min(K, row0 + BM) : K;

    __shared__ float As[BKK][BM];
    __shared__ float Bs[BKK][BN];

    const int tid  = threadIdx.x;
    const int aRow = tid >> 1;            // 0..127
    const int aK   = (tid & 1) * 4;       // 0 or 4
    const int bK   = tid >> 5;            // 0..7   (NN path)
    const int bCol = (tid & 31) * 4;      // 0..124 (NN path)
    const int ty   = tid >> 4;            // 0..15
    const int tx   = tid & 15;            // 0..15

    float acc[TM][TN];
    #pragma unroll
    for (int i = 0; i < TM; i++)
        #pragma unroll
        for (int j = 0; j < TN; j++) acc[i][j] = 0.f;

    const float* Aptr = A + (size_t)(row0 + aRow) * lda + aK;

    for (int k0 = 0; k0 < Keff; k0 += BKK) {
        // --- A tile (M always multiple of 128, K multiple of 8 here) ---
        float4 av = *reinterpret_cast<const float4*>(Aptr + k0);
        As[aK + 0][aRow] = av.x;
        As[aK + 1][aRow] = av.y;
        As[aK + 2][aRow] = av.z;
        As[aK + 3][aRow] = av.w;
        // --- B tile ---
        if (!TRANSB) {
            int gc = col0 + bCol;
            const float* Bp = B + (size_t)(k0 + bK) * ldb + gc;
            if (gc + 3 < N) {
                float4 bv = *reinterpret_cast<const float4*>(Bp);
                Bs[bK][bCol + 0] = bv.x;  Bs[bK][bCol + 1] = bv.y;
                Bs[bK][bCol + 2] = bv.z;  Bs[bK][bCol + 3] = bv.w;
            } else {
                #pragma unroll
                for (int i = 0; i < 4; i++)
                    Bs[bK][bCol + i] = (gc + i < N) ? Bp[i] : 0.f;
            }
        } else {
            // B is [N,K]; Bs[k][n] = B[col0+n][k0+k]; only used with N % 128 == 0
            int n  = tid >> 1;
            int kk = (tid & 1) * 4;
            const float* Bp = B + (size_t)(col0 + n) * ldb + k0 + kk;
            float4 bv = *reinterpret_cast<const float4*>(Bp);
            Bs[kk + 0][n] = bv.x;  Bs[kk + 1][n] = bv.y;
            Bs[kk + 2][n] = bv.z;  Bs[kk + 3][n] = bv.w;
        }
        __syncthreads();

        #pragma unroll
        for (int kk = 0; kk < BKK; kk++) {
            float a[TM], b[TN];
            #pragma unroll
            for (int i = 0; i < TM; i++) a[i] = As[kk][ty * TM + i];
            #pragma unroll
            for (int j = 0; j < TN; j++) b[j] = Bs[kk][tx * TN + j];
            #pragma unroll
            for (int i = 0; i < TM; i++)
                #pragma unroll
                for (int j = 0; j < TN; j++)
                    acc[i][j] = fmaf(a[i], b[j], acc[i][j]);
        }
        __syncthreads();
    }

    #pragma unroll
    for (int i = 0; i < TM; i++) {
        int r = row0 + ty * TM + i;
        #pragma unroll
        for (int j = 0; j < TN; j++) {
            int c = col0 + tx * TN + j;
            if (c < N) C[(size_t)r * ldc + c] = acc[i][j];
        }
    }
}

// ---------------- RMSNorm on q_a rows (len 1536) ----------------
__global__ __launch_bounds__(256)
void rms_q_kernel(const float* __restrict__ in, const float* __restrict__ w,
                  float* __restrict__ out)
{
    const int s = blockIdx.x;
    const float* x = in + (size_t)s * QL_;
    float*       y = out + (size_t)s * QL_;
    const int tid = threadIdx.x;

    float v[6];
    float local = 0.f;
    #pragma unroll
    for (int i = 0; i < 6; i++) {
        int c = tid + i * 256;
        v[i] = x[c];
        local += v[i] * v[i];
    }
    __shared__ float sred[256];
    sred[tid] = local; __syncthreads();
    for (int st = 128; st > 0; st >>= 1) {
        if (tid < st) sred[tid] += sred[tid + st];
        __syncthreads();
    }
    float scale = rsqrtf(sred[0] / (float)QL_ + EPS_);
    #pragma unroll
    for (int i = 0; i < 6; i++) {
        int c = tid + i * 256;
        y[c] = v[i] * scale * w[c];
    }
}

// ---------------- RMSNorm ckv[:512] + RoPE on k_pe; also writes kv_cache ----------------
__global__ __launch_bounds__(256)
void rms_ckv_kernel(const float* __restrict__ ckv, const float* __restrict__ w,
                    const float* __restrict__ cosT, const float* __restrict__ sinT,
                    const int* __restrict__ pos,
                    float* __restrict__ cnorm, float* __restrict__ kpe,
                    float* __restrict__ cache)
{
    const int s = blockIdx.x;
    const float* x = ckv + (size_t)s * CKV_W;
    const int tid = threadIdx.x;

    float v[2];
    float local = 0.f;
    #pragma unroll
    for (int i = 0; i < 2; i++) {
        int c = tid + i * 256;
        v[i] = x[c];
        local += v[i] * v[i];
    }
    __shared__ float sred[256];
    sred[tid] = local; __syncthreads();
    for (int st = 128; st > 0; st >>= 1) {
        if (tid < st) sred[tid] += sred[tid + st];
        __syncthreads();
    }
    float scale = rsqrtf(sred[0] / (float)KVL_ + EPS_);
    #pragma unroll
    for (int i = 0; i < 2; i++) {
        int c = tid + i * 256;
        float y = v[i] * scale * w[c];
        cnorm[(size_t)s * KVL_ + c] = y;
        cache[(size_t)s * CKV_W + c] = y;
    }
    // RoPE on k_pe (64 dims): x_perm = [x[0::2], x[1::2]]; out = x_perm*cos + rot_half(x_perm)*sin
    if (tid < D_ROPE) {
        int p = pos[s];
        const float* cr = cosT + (size_t)p * D_ROPE;
        const float* sr = sinT + (size_t)p * D_ROPE;
        const float* t  = x + KVL_;
        int i = tid;
        float val;
        if (i < 32) val = t[2 * i] * cr[i] - t[2 * i + 1] * sr[i];
        else { int i2 = i - 32; val = t[2 * i2 + 1] * cr[i] + t[2 * i2] * sr[i]; }
        kpe[(size_t)s * D_ROPE + i] = val;
        cache[(size_t)s * CKV_W + KVL_ + i] = val;
    }
}

// ---------------- assemble per-head Q (with RoPE), K, V ----------------
__global__ void assemble_kernel(const float* __restrict__ q, const float* __restrict__ kv,
                                const float* __restrict__ kpe,
                                const float* __restrict__ cosT, const float* __restrict__ sinT,
                                const int* __restrict__ pos,
                                float* __restrict__ Q, float* __restrict__ K,
                                float* __restrict__ V)
{
    const int s = blockIdx.x;
    const int h = blockIdx.y;
    const int d = threadIdx.x;  // 0..191
    const float* qrow  = q  + (size_t)s * QDIM  + h * QHEAD;
    const float* kvrow = kv + (size_t)s * KVDIM + h * (D_NOPE + D_V);
    const size_t off = ((size_t)h * S_ + s) * QHEAD;

    float qv;
    if (d < D_NOPE) qv = qrow[d];
    else {
        int p = pos[s];
        const float* cr = cosT + (size_t)p * D_ROPE;
        const float* sr = sinT + (size_t)p * D_ROPE;
        const float* t  = qrow + D_NOPE;
        int i = d - D_NOPE;
        if (i < 32) qv = t[2 * i] * cr[i] - t[2 * i + 1] * sr[i];
        else { int i2 = i - 32; qv = t[2 * i2 + 1] * cr[i] + t[2 * i2] * sr[i]; }
    }
    Q[off + d] = qv;
    K[off + d] = (d < D_NOPE) ? kvrow[d] : kpe[(size_t)s * D_ROPE + (d - D_NOPE)];
    if (d < D_V) V[((size_t)h * S_ + s) * D_V + d] = kvrow[D_NOPE + d];
}

// ---------------- masked softmax over score rows (scale + mask + softmax) ----------------
__global__ __launch_bounds__(256)
void softmax_kernel(float* __restrict__ scores, const float* __restrict__ mask)
{
    const int s = blockIdx.x;
    const int h = blockIdx.y;
    float* row = scores + ((size_t)h * S_ + s) * S_;
    const float* mrow = mask + (size_t)s * S_;
    const int tid = threadIdx.x;

    float v[8];
    float m = -1e30f;
    #pragma unroll
    for (int i = 0; i < 8; i++) {
        int c = tid + i * 256;
        v[i] = row[c] * SCALE_ + mrow[c];
        m = fmaxf(m, v[i]);
    }
    __shared__ float sred[256];
    sred[tid] = m; __syncthreads();
    for (int st = 128; st > 0; st >>= 1) {
        if (tid < st) sred[tid] = fmaxf(sred[tid], sred[tid + st]);
        __syncthreads();
    }
    m = sred[0];
    __syncthreads();

    float sum = 0.f;
    #pragma unroll
    for (int i = 0; i < 8; i++) {
        v[i] = __expf(v[i] - m);
        sum += v[i];
    }
    sred[tid] = sum; __syncthreads();
    for (int st = 128; st > 0; st >>= 1) {
        if (tid < st) sred[tid] += sred[tid + st];
        __syncthreads();
    }
    float inv = 1.f / sred[0];
    #pragma unroll
    for (int i = 0; i < 8; i++) {
        int c = tid + i * 256;
        row[c] = v[i] * inv;
    }
}

// ---------------- host launch ----------------
extern "C" void kernel_launch(void* const* d_in, const int* in_sizes, int n_in,
                              void* d_out, int out_size)
{
    const float* x       = (const float*)d_in[0];
    const float* mask    = (const float*)d_in[1];
    const int*   pos     = (const int*)  d_in[2];
    const float* cosT    = (const float*)d_in[3];
    const float* sinT    = (const float*)d_in[4];
    const float* q_a_w   = (const float*)d_in[5];
    const float* q_a_ln  = (const float*)d_in[6];
    const float* q_b_w   = (const float*)d_in[7];
    const float* kv_a_w  = (const float*)d_in[8];
    const float* kv_a_ln = (const float*)d_in[9];
    const float* kv_b_w  = (const float*)d_in[10];
    const float* o_w     = (const float*)d_in[11];
    float* out = (float*)d_out;
    float* out_cache = out + (size_t)S_ * HID_;   // kv_cache after main output

    float *qa, *qn, *ckv, *cnorm, *kpe, *q, *kv, *Q, *K, *V, *scores, *attn;
    cudaGetSymbolAddress((void**)&qa,     g_qa);
    cudaGetSymbolAddress((void**)&qn,     g_qn);
    cudaGetSymbolAddress((void**)&ckv,    g_ckv);
    cudaGetSymbolAddress((void**)&cnorm,  g_cnorm);
    cudaGetSymbolAddress((void**)&kpe,    g_kpe);
    cudaGetSymbolAddress((void**)&q,      g_q);
    cudaGetSymbolAddress((void**)&kv,     g_kv);
    cudaGetSymbolAddress((void**)&Q,      g_Q);
    cudaGetSymbolAddress((void**)&K,      g_K);
    cudaGetSymbolAddress((void**)&V,      g_V);
    cudaGetSymbolAddress((void**)&scores, g_scores);
    cudaGetSymbolAddress((void**)&attn,   g_attn);

    dim3 blk(256);

    // 1) q_a = x @ q_a_w   [2048,2048]x[2048,1536]
    sgemm_kernel<false><<<dim3(QL_/BN, S_/BM, 1), blk>>>(
        x, HID_, 0, q_a_w, QL_, 0, qa, QL_, 0, S_, QL_, HID_, 0);
    // 2) ckv = x @ kv_a_w  [2048,2048]x[2048,576]
    sgemm_kernel<false><<<dim3((CKV_W+BN-1)/BN, S_/BM, 1), blk>>>(
        x, HID_, 0, kv_a_w, CKV_W, 0, ckv, CKV_W, 0, S_, CKV_W, HID_, 0);
    // 3) RMSNorm q_a
    rms_q_kernel<<<S_, blk>>>(qa, q_a_ln, qn);
    // 4) RMSNorm ckv[:,:512] + RoPE k_pe + write kv_cache
    rms_ckv_kernel<<<S_, blk>>>(ckv, kv_a_ln, cosT, sinT, pos, cnorm, kpe, out_cache);
    // 5) q = qn @ q_b_w   [2048,1536]x[1536,3072]
    sgemm_kernel<false><<<dim3(QDIM/BN, S_/BM, 1), blk>>>(
        qn, QL_, 0, q_b_w, QDIM, 0, q, QDIM, 0, S_, QDIM, QL_, 0);
    // 6) kv = cnorm @ kv_b_w [2048,512]x[512,4096]
    sgemm_kernel<false><<<dim3(KVDIM/BN, S_/BM, 1), blk>>>(
        cnorm, KVL_, 0, kv_b_w, KVDIM, 0, kv, KVDIM, 0, S_, KVDIM, KVL_, 0);
    // 7) assemble per-head Q (roped), K, V
    assemble_kernel<<<dim3(S_, H_), dim3(QHEAD)>>>(q, kv, kpe, cosT, sinT, pos, Q, K, V);
    // 8) scores[h] = Q[h] @ K[h]^T  (batched NT, skip fully-masked tiles)
    sgemm_kernel<true><<<dim3(S_/BN, S_/BM, H_), blk>>>(
        Q, QHEAD, (size_t)S_*QHEAD, K, QHEAD, (size_t)S_*QHEAD,
        scores, S_, (size_t)S_*S_, S_, S_, QHEAD, 1);
    // 9) softmax with scale + mask
    softmax_kernel<<<dim3(S_, H_), blk>>>(scores, mask);
    // 10) attn[s, h*128+d] = P[h] @ V[h]  (batched NN, K limited to causal frontier)
    sgemm_kernel<false><<<dim3(1, S_/BM, H_), blk>>>(
        scores, S_, (size_t)S_*S_, V, D_V, (size_t)S_*D_V,
        attn, H_*D_V, (size_t)D_V, S_, D_V, S_, 2);
    // 11) out = attn @ o_w  [2048,2048]x[2048,2048]
    sgemm_kernel<false><<<dim3(HID_/BN, S_/BM, 1), blk>>>(
        attn, H_*D_V, 0, o_w, HID_, 0, out, HID_, 0, S_, HID_, H_*D_V, 0);
}

// round 3
// speedup vs baseline: 1.8096x; 1.8096x over previous
#include <cuda_runtime.h>
#include <cuda_bf16.h>
#include <mma.h>
#include <math.h>
#include <stdint.h>

using namespace nvcuda;

// ---------------- problem constants ----------------
#define S_      2048
#define HID_    2048
#define H_      16
#define D_NOPE  128
#define D_ROPE  64
#define D_V     128
#define QHEAD   192
#define QL_     1536
#define KVL_    512
#define CKV_W   576
#define QDIM    3072
#define KVDIM   4096
#define EPS_    1e-6f
#define SCALE_  0.07216878364870322f

// ---------------- scratch ----------------
__device__ float g_qa    [S_ * QL_];
__device__ float g_qn    [S_ * QL_];
__device__ float g_ckv   [S_ * CKV_W];
__device__ float g_cnorm [S_ * KVL_];
__device__ float g_kpe   [S_ * D_ROPE];
__device__ float g_q     [S_ * QDIM];
__device__ float g_kv    [S_ * KVDIM];
__device__ float g_Q     [H_ * S_ * QHEAD];
__device__ float g_K     [H_ * S_ * QHEAD];
__device__ float g_V     [H_ * S_ * D_V];
__device__ float g_scores[(size_t)H_ * S_ * S_];
__device__ float g_attn  [S_ * (H_ * D_V)];

// tf32 round (rna) kept in an f32 container
__device__ __forceinline__ float tf32r(float f) {
    uint32_t r; asm("cvt.rna.tf32.f32 %0, %1;" : "=r"(r) : "f"(f));
    return __uint_as_float(r);
}

// ---------------- SMEM geometry ----------------
#define BK     32
#define A_STR  40    // 32 + 8 pad (floats)
#define B_STRN 136   // 128 + 8 pad (floats), NN layout [BK][128]
#define A_BYTES (128 * A_STR * 4)     // 20480
#define B_BYTES_NN (BK * B_STRN * 4)  // 17408
#define B_BYTES_NT (128 * A_STR * 4)  // 20480
#define STAGE   (A_BYTES + 20480)     // use max(B) = 20480
#define SMEM_REQ (2 * STAGE)          // 81920

// ---------------- wmma tf32 GEMM ----------------
// C[M,N] = A[M,K] * B ; TRANSB: B is [N,K] row-major (NT); else [K,N] row-major (NN)
// causal_mode: 1 = skip tiles fully above diagonal; 2 = Keff = min(K, row0+128)
template<bool TRANSB>
__global__ __launch_bounds__(256, 1)
void wgemm_kernel(const float* __restrict__ A, int lda, size_t sA,
                  const float* __restrict__ B, int ldb, size_t sB,
                  float* __restrict__ C, int ldc, size_t sC,
                  int N, int K, int causal_mode)
{
    const int bz = blockIdx.z;
    A += (size_t)bz * sA;  B += (size_t)bz * sB;  C += (size_t)bz * sC;

    const int row0 = blockIdx.y * 128;
    const int col0 = blockIdx.x * 128;
    if (causal_mode == 1 && col0 > row0 + 127) return;
    const int Keff = (causal_mode == 2) ? min(K, row0 + 128) : K;
    const int nk = Keff / BK;

    extern __shared__ char smem[];

    const int tid = threadIdx.x;
    const int wid = tid >> 5;
    const int wm  = wid >> 2;       // 0..1  -> m offset wm*64
    const int wn  = wid & 3;        // 0..3  -> n offset wn*32

    typedef wmma::fragment<wmma::matrix_a, 16, 16, 8, wmma::precision::tf32, wmma::row_major> AFrag;
    typedef typename std::conditional<TRANSB,
        wmma::fragment<wmma::matrix_b, 16, 16, 8, wmma::precision::tf32, wmma::col_major>,
        wmma::fragment<wmma::matrix_b, 16, 16, 8, wmma::precision::tf32, wmma::row_major>>::type BFrag;

    wmma::fragment<wmma::accumulator, 16, 16, 8, float> acc[4][2];
    #pragma unroll
    for (int i = 0; i < 4; i++)
        #pragma unroll
        for (int j = 0; j < 2; j++) wmma::fill_fragment(acc[i][j], 0.0f);

    float4 pa[4], pb[4];

    auto ldgA = [&](int k0) {
        #pragma unroll
        for (int i = 0; i < 4; i++) {
            int idx = i * 256 + tid;
            int r = idx >> 3, kq = idx & 7;
            pa[i] = *reinterpret_cast<const float4*>(
                A + (size_t)(row0 + r) * lda + k0 + kq * 4);
        }
    };
    auto stsA = [&](int st) {
        float* As = reinterpret_cast<float*>(smem + st * STAGE);
        #pragma unroll
        for (int i = 0; i < 4; i++) {
            int idx = i * 256 + tid;
            int r = idx >> 3, kq = idx & 7;
            float* p = As + r * A_STR + kq * 4;
            p[0] = tf32r(pa[i].x); p[1] = tf32r(pa[i].y);
            p[2] = tf32r(pa[i].z); p[3] = tf32r(pa[i].w);
        }
    };
    auto ldgB = [&](int k0) {
        if (TRANSB) {
            #pragma unroll
            for (int i = 0; i < 4; i++) {
                int idx = i * 256 + tid;
                int n = idx >> 3, kq = idx & 7;
                pb[i] = *reinterpret_cast<const float4*>(
                    B + (size_t)(col0 + n) * ldb + k0 + kq * 4);
            }
        } else {
            #pragma unroll
            for (int i = 0; i < 4; i++) {
                int idx = i * 256 + tid;
                int kr = idx >> 5, nq = idx & 31;
                int gc = col0 + nq * 4;
                if (gc + 4 <= N) {
                    pb[i] = *reinterpret_cast<const float4*>(
                        B + (size_t)(k0 + kr) * ldb + gc);
                } else {
                    const float* Bp = B + (size_t)(k0 + kr) * ldb;
                    pb[i].x = (gc + 0 < N) ? Bp[gc + 0] : 0.f;
                    pb[i].y = (gc + 1 < N) ? Bp[gc + 1] : 0.f;
                    pb[i].z = (gc + 2 < N) ? Bp[gc + 2] : 0.f;
                    pb[i].w = (gc + 3 < N) ? Bp[gc + 3] : 0.f;
                }
            }
        }
    };
    auto stsB = [&](int st) {
        float* Bs = reinterpret_cast<float*>(smem + st * STAGE + A_BYTES);
        if (TRANSB) {
            #pragma unroll
            for (int i = 0; i < 4; i++) {
                int idx = i * 256 + tid;
                int n = idx >> 3, kq = idx & 7;
                float* p = Bs + n * A_STR + kq * 4;
                p[0] = tf32r(pb[i].x); p[1] = tf32r(pb[i].y);
                p[2] = tf32r(pb[i].z); p[3] = tf32r(pb[i].w);
            }
        } else {
            #pragma unroll
            for (int i = 0; i < 4; i++) {
                int idx = i * 256 + tid;
                int kr = idx >> 5, nq = idx & 31;
                float* p = Bs + kr * B_STRN + nq * 4;
                p[0] = tf32r(pb[i].x); p[1] = tf32r(pb[i].y);
                p[2] = tf32r(pb[i].z); p[3] = tf32r(pb[i].w);
            }
        }
    };

    // preload tile 0
    ldgA(0); ldgB(0);
    stsA(0); stsB(0);
    __syncthreads();

    for (int t = 0; t < nk; t++) {
        const int st = t & 1;
        if (t + 1 < nk) { ldgA((t + 1) * BK); ldgB((t + 1) * BK); }

        const float* As = reinterpret_cast<const float*>(smem + st * STAGE);
        const float* Bs = reinterpret_cast<const float*>(smem + st * STAGE + A_BYTES);

        #pragma unroll
        for (int kk = 0; kk < 4; kk++) {
            AFrag af[4];
            BFrag bf[2];
            #pragma unroll
            for (int mf = 0; mf < 4; mf++)
                wmma::load_matrix_sync(af[mf], As + (wm * 64 + mf * 16) * A_STR + kk * 8, A_STR);
            #pragma unroll
            for (int nf = 0; nf < 2; nf++) {
                if (TRANSB)
                    wmma::load_matrix_sync(bf[nf], Bs + (wn * 32 + nf * 16) * A_STR + kk * 8, A_STR);
                else
                    wmma::load_matrix_sync(bf[nf], Bs + (kk * 8) * B_STRN + wn * 32 + nf * 16, B_STRN);
            }
            #pragma unroll
            for (int mf = 0; mf < 4; mf++)
                #pragma unroll
                for (int nf = 0; nf < 2; nf++)
                    wmma::mma_sync(acc[mf][nf], af[mf], bf[nf], acc[mf][nf]);
        }

        if (t + 1 < nk) { stsA(st ^ 1); stsB(st ^ 1); }
        __syncthreads();
    }

    // epilogue: direct global store (fragments never straddle the N edge: edges are /64)
    #pragma unroll
    for (int mf = 0; mf < 4; mf++) {
        int gr = row0 + wm * 64 + mf * 16;
        #pragma unroll
        for (int nf = 0; nf < 2; nf++) {
            int gc = col0 + wn * 32 + nf * 16;
            if (gc + 16 <= N)
                wmma::store_matrix_sync(C + (size_t)gr * ldc + gc, acc[mf][nf], ldc,
                                        wmma::mem_row_major);
        }
    }
}

// ---------------- RMSNorm q_a ----------------
__global__ __launch_bounds__(256)
void rms_q_kernel(const float* __restrict__ in, const float* __restrict__ w,
                  float* __restrict__ out)
{
    const int s = blockIdx.x;
    const float* x = in + (size_t)s * QL_;
    float*       y = out + (size_t)s * QL_;
    const int tid = threadIdx.x;

    float v[6];
    float local = 0.f;
    #pragma unroll
    for (int i = 0; i < 6; i++) { int c = tid + i * 256; v[i] = x[c]; local += v[i] * v[i]; }
    __shared__ float sred[256];
    sred[tid] = local; __syncthreads();
    for (int st = 128; st > 0; st >>= 1) {
        if (tid < st) sred[tid] += sred[tid + st];
        __syncthreads();
    }
    float scale = rsqrtf(sred[0] / (float)QL_ + EPS_);
    #pragma unroll
    for (int i = 0; i < 6; i++) { int c = tid + i * 256; y[c] = v[i] * scale * w[c]; }
}

// ---------------- RMSNorm ckv + RoPE k_pe + kv_cache ----------------
__global__ __launch_bounds__(256)
void rms_ckv_kernel(const float* __restrict__ ckv, const float* __restrict__ w,
                    const float* __restrict__ cosT, const float* __restrict__ sinT,
                    const int* __restrict__ pos,
                    float* __restrict__ cnorm, float* __restrict__ kpe,
                    float* __restrict__ cache)
{
    const int s = blockIdx.x;
    const float* x = ckv + (size_t)s * CKV_W;
    const int tid = threadIdx.x;

    float v[2];
    float local = 0.f;
    #pragma unroll
    for (int i = 0; i < 2; i++) { int c = tid + i * 256; v[i] = x[c]; local += v[i] * v[i]; }
    __shared__ float sred[256];
    sred[tid] = local; __syncthreads();
    for (int st = 128; st > 0; st >>= 1) {
        if (tid < st) sred[tid] += sred[tid + st];
        __syncthreads();
    }
    float scale = rsqrtf(sred[0] / (float)KVL_ + EPS_);
    #pragma unroll
    for (int i = 0; i < 2; i++) {
        int c = tid + i * 256;
        float y = v[i] * scale * w[c];
        cnorm[(size_t)s * KVL_ + c] = y;
        cache[(size_t)s * CKV_W + c] = y;
    }
    if (tid < D_ROPE) {
        int p = pos[s];
        const float* cr = cosT + (size_t)p * D_ROPE;
        const float* sr = sinT + (size_t)p * D_ROPE;
        const float* t  = x + KVL_;
        int i = tid;
        float val;
        if (i < 32) val = t[2 * i] * cr[i] - t[2 * i + 1] * sr[i];
        else { int i2 = i - 32; val = t[2 * i2 + 1] * cr[i] + t[2 * i2] * sr[i]; }
        kpe[(size_t)s * D_ROPE + i] = val;
        cache[(size_t)s * CKV_W + KVL_ + i] = val;
    }
}

// ---------------- assemble Q (roped), K, V ----------------
__global__ void assemble_kernel(const float* __restrict__ q, const float* __restrict__ kv,
                                const float* __restrict__ kpe,
                                const float* __restrict__ cosT, const float* __restrict__ sinT,
                                const int* __restrict__ pos,
                                float* __restrict__ Q, float* __restrict__ K,
                                float* __restrict__ V)
{
    const int s = blockIdx.x;
    const int h = blockIdx.y;
    const int d = threadIdx.x;
    const float* qrow  = q  + (size_t)s * QDIM  + h * QHEAD;
    const float* kvrow = kv + (size_t)s * KVDIM + h * (D_NOPE + D_V);
    const size_t off = ((size_t)h * S_ + s) * QHEAD;

    float qv;
    if (d < D_NOPE) qv = qrow[d];
    else {
        int p = pos[s];
        const float* cr = cosT + (size_t)p * D_ROPE;
        const float* sr = sinT + (size_t)p * D_ROPE;
        const float* t  = qrow + D_NOPE;
        int i = d - D_NOPE;
        if (i < 32) qv = t[2 * i] * cr[i] - t[2 * i + 1] * sr[i];
        else { int i2 = i - 32; qv = t[2 * i2 + 1] * cr[i] + t[2 * i2] * sr[i]; }
    }
    Q[off + d] = qv;
    K[off + d] = (d < D_NOPE) ? kvrow[d] : kpe[(size_t)s * D_ROPE + (d - D_NOPE)];
    if (d < D_V) V[((size_t)h * S_ + s) * D_V + d] = kvrow[D_NOPE + d];
}

// ---------------- softmax ----------------
__global__ __launch_bounds__(256)
void softmax_kernel(float* __restrict__ scores, const float* __restrict__ mask)
{
    const int s = blockIdx.x;
    const int h = blockIdx.y;
    float* row = scores + ((size_t)h * S_ + s) * S_;
    const float* mrow = mask + (size_t)s * S_;
    const int tid = threadIdx.x;

    float v[8];
    float m = -1e30f;
    #pragma unroll
    for (int i = 0; i < 8; i++) {
        int c = tid + i * 256;
        v[i] = row[c] * SCALE_ + mrow[c];
        m = fmaxf(m, v[i]);
    }
    __shared__ float sred[256];
    sred[tid] = m; __syncthreads();
    for (int st = 128; st > 0; st >>= 1) {
        if (tid < st) sred[tid] = fmaxf(sred[tid], sred[tid + st]);
        __syncthreads();
    }
    m = sred[0];
    __syncthreads();

    float sum = 0.f;
    #pragma unroll
    for (int i = 0; i < 8; i++) { v[i] = __expf(v[i] - m); sum += v[i]; }
    sred[tid] = sum; __syncthreads();
    for (int st = 128; st > 0; st >>= 1) {
        if (tid < st) sred[tid] += sred[tid + st];
        __syncthreads();
    }
    float inv = 1.f / sred[0];
    #pragma unroll
    for (int i = 0; i < 8; i++) { int c = tid + i * 256; row[c] = v[i] * inv; }
}

// ---------------- host launch ----------------
extern "C" void kernel_launch(void* const* d_in, const int* in_sizes, int n_in,
                              void* d_out, int out_size)
{
    const float* x       = (const float*)d_in[0];
    const float* mask    = (const float*)d_in[1];
    const int*   pos     = (const int*)  d_in[2];
    const float* cosT    = (const float*)d_in[3];
    const float* sinT    = (const float*)d_in[4];
    const float* q_a_w   = (const float*)d_in[5];
    const float* q_a_ln  = (const float*)d_in[6];
    const float* q_b_w   = (const float*)d_in[7];
    const float* kv_a_w  = (const float*)d_in[8];
    const float* kv_a_ln = (const float*)d_in[9];
    const float* kv_b_w  = (const float*)d_in[10];
    const float* o_w     = (const float*)d_in[11];
    float* out = (float*)d_out;
    float* out_cache = out + (size_t)S_ * HID_;

    float *qa, *qn, *ckv, *cnorm, *kpe, *q, *kv, *Q, *K, *V, *scores, *attn;
    cudaGetSymbolAddress((void**)&qa,     g_qa);
    cudaGetSymbolAddress((void**)&qn,     g_qn);
    cudaGetSymbolAddress((void**)&ckv,    g_ckv);
    cudaGetSymbolAddress((void**)&cnorm,  g_cnorm);
    cudaGetSymbolAddress((void**)&kpe,    g_kpe);
    cudaGetSymbolAddress((void**)&q,      g_q);
    cudaGetSymbolAddress((void**)&kv,     g_kv);
    cudaGetSymbolAddress((void**)&Q,      g_Q);
    cudaGetSymbolAddress((void**)&K,      g_K);
    cudaGetSymbolAddress((void**)&V,      g_V);
    cudaGetSymbolAddress((void**)&scores, g_scores);
    cudaGetSymbolAddress((void**)&attn,   g_attn);

    cudaFuncSetAttribute(wgemm_kernel<false>, cudaFuncAttributeMaxDynamicSharedMemorySize, SMEM_REQ);
    cudaFuncSetAttribute(wgemm_kernel<true>,  cudaFuncAttributeMaxDynamicSharedMemorySize, SMEM_REQ);

    dim3 blk(256);

    // 1) q_a = x @ q_a_w
    wgemm_kernel<false><<<dim3(QL_/128, S_/128, 1), blk, SMEM_REQ>>>(
        x, HID_, 0, q_a_w, QL_, 0, qa, QL_, 0, QL_, HID_, 0);
    // 2) ckv = x @ kv_a_w (N=576, last tile partial)
    wgemm_kernel<false><<<dim3((CKV_W+127)/128, S_/128, 1), blk, SMEM_REQ>>>(
        x, HID_, 0, kv_a_w, CKV_W, 0, ckv, CKV_W, 0, CKV_W, HID_, 0);
    // 3) RMSNorm q_a
    rms_q_kernel<<<S_, blk>>>(qa, q_a_ln, qn);
    // 4) RMSNorm ckv + RoPE k_pe + kv_cache
    rms_ckv_kernel<<<S_, blk>>>(ckv, kv_a_ln, cosT, sinT, pos, cnorm, kpe, out_cache);
    // 5) q = qn @ q_b_w
    wgemm_kernel<false><<<dim3(QDIM/128, S_/128, 1), blk, SMEM_REQ>>>(
        qn, QL_, 0, q_b_w, QDIM, 0, q, QDIM, 0, QDIM, QL_, 0);
    // 6) kv = cnorm @ kv_b_w
    wgemm_kernel<false><<<dim3(KVDIM/128, S_/128, 1), blk, SMEM_REQ>>>(
        cnorm, KVL_, 0, kv_b_w, KVDIM, 0, kv, KVDIM, 0, KVDIM, KVL_, 0);
    // 7) assemble
    assemble_kernel<<<dim3(S_, H_), dim3(QHEAD)>>>(q, kv, kpe, cosT, sinT, pos, Q, K, V);
    // 8) scores[h] = Q[h] @ K[h]^T (NT, causal skip)
    wgemm_kernel<true><<<dim3(S_/128, S_/128, H_), blk, SMEM_REQ>>>(
        Q, QHEAD, (size_t)S_*QHEAD, K, QHEAD, (size_t)S_*QHEAD,
        scores, S_, (size_t)S_*S_, S_, QHEAD, 1);
    // 9) softmax
    softmax_kernel<<<dim3(S_, H_), blk>>>(scores, mask);
    // 10) attn = P @ V (NN, K limited to causal frontier)
    wgemm_kernel<false><<<dim3(1, S_/128, H_), blk, SMEM_REQ>>>(
        scores, S_, (size_t)S_*S_, V, D_V, (size_t)S_*D_V,
        attn, H_*D_V, (size_t)D_V, D_V, S_, 2);
    // 11) out = attn @ o_w
    wgemm_kernel<false><<<dim3(HID_/128, S_/128, 1), blk, SMEM_REQ>>>(
        attn, H_*D_V, 0, o_w, HID_, 0, out, HID_, 0, HID_, H_*D_V, 0);
}

// round 4
// speedup vs baseline: 1.8364x; 1.0148x over previous
#include <cuda_runtime.h>
#include <cuda_bf16.h>
#include <mma.h>
#include <math.h>
#include <stdint.h>

using namespace nvcuda;

// ---------------- problem constants ----------------
#define S_      2048
#define HID_    2048
#define H_      16
#define D_NOPE  128
#define D_ROPE  64
#define D_V     128
#define QHEAD   192
#define QL_     1536
#define KVL_    512
#define CKV_W   576
#define QDIM    3072
#define KVDIM   4096
#define EPS_    1e-6f
#define SCALE_  0.07216878364870322f

// ---------------- scratch ----------------
__device__ float g_qa    [S_ * QL_];
__device__ float g_qn    [S_ * QL_];
__device__ float g_ckv   [S_ * CKV_W];
__device__ float g_cnorm [S_ * KVL_];
__device__ float g_kpe   [S_ * D_ROPE];
__device__ float g_q     [S_ * QDIM];
__device__ float g_kv    [S_ * KVDIM];
__device__ float g_Q     [H_ * S_ * QHEAD];   // tf32-rounded, dim-permuted
__device__ float g_K     [H_ * S_ * QHEAD];   // tf32-rounded, dim-permuted
__device__ float g_V     [H_ * S_ * D_V];     // tf32-rounded, natural
__device__ float g_attn  [S_ * (H_ * D_V)];

// tf32 round (rna) kept in an f32 container
__device__ __forceinline__ float tf32r(float f) {
    uint32_t r; asm("cvt.rna.tf32.f32 %0, %1;" : "=r"(r) : "f"(f));
    return __uint_as_float(r);
}
// permutation within 8-groups: storage[2t]=natural t, storage[2t+1]=natural t+4
__device__ __forceinline__ int perm8(int c) {
    return (c & ~7) | ((c & 3) << 1) | ((c >> 2) & 1);
}
__device__ __forceinline__ uint32_t smem_u32(const void* p) {
    uint32_t a;
    asm("{ .reg .u64 t; cvta.to.shared.u64 t, %1; cvt.u32.u64 %0, t; }" : "=r"(a) : "l"(p));
    return a;
}
__device__ __forceinline__ void cp16(uint32_t d, const void* s) {
    asm volatile("cp.async.ca.shared.global [%0], [%1], 16;" :: "r"(d), "l"(s));
}
__device__ __forceinline__ void cp_commit() {
    asm volatile("cp.async.commit_group;" ::: "memory");
}
template<int N> __device__ __forceinline__ void cp_wait() {
    asm volatile("cp.async.wait_group %0;" :: "n"(N) : "memory");
}
// m16n8k8 tf32 mma, acc fp32 (a0:(g,t) a1:(g+8,t) a2:(g,t+4) a3:(g+8,t+4); b0:(k=t,n=g) b1:(k=t+4,n=g))
__device__ __forceinline__ void mma8(float* c, uint32_t a0, uint32_t a1, uint32_t a2, uint32_t a3,
                                     uint32_t b0, uint32_t b1) {
    asm volatile(
        "mma.sync.aligned.m16n8k8.row.col.f32.tf32.tf32.f32 "
        "{%0,%1,%2,%3}, {%4,%5,%6,%7}, {%8,%9}, {%0,%1,%2,%3};"
        : "+f"(c[0]), "+f"(c[1]), "+f"(c[2]), "+f"(c[3])
        : "r"(a0), "r"(a1), "r"(a2), "r"(a3), "r"(b0), "r"(b1));
}

// ---------------- wmma tf32 GEMM (projections) ----------------
#define BK     32
#define A_STR  40
#define B_STRN 136
#define A_BYTES (128 * A_STR * 4)
#define STAGE   (A_BYTES + 20480)
#define SMEM_REQ (2 * STAGE)

__global__ __launch_bounds__(256, 1)
void wgemm_kernel(const float* __restrict__ A, int lda,
                  const float* __restrict__ B, int ldb,
                  float* __restrict__ C, int ldc,
                  int N, int K)
{
    const int row0 = blockIdx.y * 128;
    const int col0 = blockIdx.x * 128;
    const int nk = K / BK;

    extern __shared__ char smem[];
    const int tid = threadIdx.x;
    const int wid = tid >> 5;
    const int wm  = wid >> 2;
    const int wn  = wid & 3;

    typedef wmma::fragment<wmma::matrix_a, 16, 16, 8, wmma::precision::tf32, wmma::row_major> AFrag;
    typedef wmma::fragment<wmma::matrix_b, 16, 16, 8, wmma::precision::tf32, wmma::row_major> BFrag;

    wmma::fragment<wmma::accumulator, 16, 16, 8, float> acc[4][2];
    #pragma unroll
    for (int i = 0; i < 4; i++)
        #pragma unroll
        for (int j = 0; j < 2; j++) wmma::fill_fragment(acc[i][j], 0.0f);

    float4 pa[4], pb[4];

    auto ldgA = [&](int k0) {
        #pragma unroll
        for (int i = 0; i < 4; i++) {
            int idx = i * 256 + tid;
            int r = idx >> 3, kq = idx & 7;
            pa[i] = *reinterpret_cast<const float4*>(A + (size_t)(row0 + r) * lda + k0 + kq * 4);
        }
    };
    auto stsA = [&](int st) {
        float* As = reinterpret_cast<float*>(smem + st * STAGE);
        #pragma unroll
        for (int i = 0; i < 4; i++) {
            int idx = i * 256 + tid;
            int r = idx >> 3, kq = idx & 7;
            float* p = As + r * A_STR + kq * 4;
            p[0] = tf32r(pa[i].x); p[1] = tf32r(pa[i].y);
            p[2] = tf32r(pa[i].z); p[3] = tf32r(pa[i].w);
        }
    };
    auto ldgB = [&](int k0) {
        #pragma unroll
        for (int i = 0; i < 4; i++) {
            int idx = i * 256 + tid;
            int kr = idx >> 5, nq = idx & 31;
            int gc = col0 + nq * 4;
            if (gc + 4 <= N) {
                pb[i] = *reinterpret_cast<const float4*>(B + (size_t)(k0 + kr) * ldb + gc);
            } else {
                const float* Bp = B + (size_t)(k0 + kr) * ldb;
                pb[i].x = (gc + 0 < N) ? Bp[gc + 0] : 0.f;
                pb[i].y = (gc + 1 < N) ? Bp[gc + 1] : 0.f;
                pb[i].z = (gc + 2 < N) ? Bp[gc + 2] : 0.f;
                pb[i].w = (gc + 3 < N) ? Bp[gc + 3] : 0.f;
            }
        }
    };
    auto stsB = [&](int st) {
        float* Bs = reinterpret_cast<float*>(smem + st * STAGE + A_BYTES);
        #pragma unroll
        for (int i = 0; i < 4; i++) {
            int idx = i * 256 + tid;
            int kr = idx >> 5, nq = idx & 31;
            float* p = Bs + kr * B_STRN + nq * 4;
            p[0] = tf32r(pb[i].x); p[1] = tf32r(pb[i].y);
            p[2] = tf32r(pb[i].z); p[3] = tf32r(pb[i].w);
        }
    };

    ldgA(0); ldgB(0);
    stsA(0); stsB(0);
    __syncthreads();

    for (int t = 0; t < nk; t++) {
        const int st = t & 1;
        if (t + 1 < nk) { ldgA((t + 1) * BK); ldgB((t + 1) * BK); }

        const float* As = reinterpret_cast<const float*>(smem + st * STAGE);
        const float* Bs = reinterpret_cast<const float*>(smem + st * STAGE + A_BYTES);

        #pragma unroll
        for (int kk = 0; kk < 4; kk++) {
            AFrag af[4];
            BFrag bf[2];
            #pragma unroll
            for (int mf = 0; mf < 4; mf++)
                wmma::load_matrix_sync(af[mf], As + (wm * 64 + mf * 16) * A_STR + kk * 8, A_STR);
            #pragma unroll
            for (int nf = 0; nf < 2; nf++)
                wmma::load_matrix_sync(bf[nf], Bs + (kk * 8) * B_STRN + wn * 32 + nf * 16, B_STRN);
            #pragma unroll
            for (int mf = 0; mf < 4; mf++)
                #pragma unroll
                for (int nf = 0; nf < 2; nf++)
                    wmma::mma_sync(acc[mf][nf], af[mf], bf[nf], acc[mf][nf]);
        }

        if (t + 1 < nk) { stsA(st ^ 1); stsB(st ^ 1); }
        __syncthreads();
    }

    #pragma unroll
    for (int mf = 0; mf < 4; mf++) {
        int gr = row0 + wm * 64 + mf * 16;
        #pragma unroll
        for (int nf = 0; nf < 2; nf++) {
            int gc = col0 + wn * 32 + nf * 16;
            if (gc + 16 <= N)
                wmma::store_matrix_sync(C + (size_t)gr * ldc + gc, acc[mf][nf], ldc,
                                        wmma::mem_row_major);
        }
    }
}

// ---------------- RMSNorm q_a ----------------
__global__ __launch_bounds__(256)
void rms_q_kernel(const float* __restrict__ in, const float* __restrict__ w,
                  float* __restrict__ out)
{
    const int s = blockIdx.x;
    const float* x = in + (size_t)s * QL_;
    float*       y = out + (size_t)s * QL_;
    const int tid = threadIdx.x;

    float v[6];
    float local = 0.f;
    #pragma unroll
    for (int i = 0; i < 6; i++) { int c = tid + i * 256; v[i] = x[c]; local += v[i] * v[i]; }
    __shared__ float sred[256];
    sred[tid] = local; __syncthreads();
    for (int st = 128; st > 0; st >>= 1) {
        if (tid < st) sred[tid] += sred[tid + st];
        __syncthreads();
    }
    float scale = rsqrtf(sred[0] / (float)QL_ + EPS_);
    #pragma unroll
    for (int i = 0; i < 6; i++) { int c = tid + i * 256; y[c] = v[i] * scale * w[c]; }
}

// ---------------- RMSNorm ckv + RoPE k_pe + kv_cache ----------------
__global__ __launch_bounds__(256)
void rms_ckv_kernel(const float* __restrict__ ckv, const float* __restrict__ w,
                    const float* __restrict__ cosT, const float* __restrict__ sinT,
                    const int* __restrict__ pos,
                    float* __restrict__ cnorm, float* __restrict__ kpe,
                    float* __restrict__ cache)
{
    const int s = blockIdx.x;
    const float* x = ckv + (size_t)s * CKV_W;
    const int tid = threadIdx.x;

    float v[2];
    float local = 0.f;
    #pragma unroll
    for (int i = 0; i < 2; i++) { int c = tid + i * 256; v[i] = x[c]; local += v[i] * v[i]; }
    __shared__ float sred[256];
    sred[tid] = local; __syncthreads();
    for (int st = 128; st > 0; st >>= 1) {
        if (tid < st) sred[tid] += sred[tid + st];
        __syncthreads();
    }
    float scale = rsqrtf(sred[0] / (float)KVL_ + EPS_);
    #pragma unroll
    for (int i = 0; i < 2; i++) {
        int c = tid + i * 256;
        float y = v[i] * scale * w[c];
        cnorm[(size_t)s * KVL_ + c] = y;
        cache[(size_t)s * CKV_W + c] = y;
    }
    if (tid < D_ROPE) {
        int p = pos[s];
        const float* cr = cosT + (size_t)p * D_ROPE;
        const float* sr = sinT + (size_t)p * D_ROPE;
        const float* t  = x + KVL_;
        int i = tid;
        float val;
        if (i < 32) val = t[2 * i] * cr[i] - t[2 * i + 1] * sr[i];
        else { int i2 = i - 32; val = t[2 * i2 + 1] * cr[i] + t[2 * i2] * sr[i]; }
        kpe[(size_t)s * D_ROPE + i] = val;
        cache[(size_t)s * CKV_W + KVL_ + i] = val;
    }
}

// ---------------- assemble Q (roped, tf32, dim-permuted), K (same), V (tf32, natural) ----------------
__global__ void assemble_kernel(const float* __restrict__ q, const float* __restrict__ kv,
                                const float* __restrict__ kpe,
                                const float* __restrict__ cosT, const float* __restrict__ sinT,
                                const int* __restrict__ pos,
                                float* __restrict__ Q, float* __restrict__ K,
                                float* __restrict__ V)
{
    const int s = blockIdx.x;
    const int h = blockIdx.y;
    const int d = threadIdx.x;
    const float* qrow  = q  + (size_t)s * QDIM  + h * QHEAD;
    const float* kvrow = kv + (size_t)s * KVDIM + h * (D_NOPE + D_V);
    const size_t off = ((size_t)h * S_ + s) * QHEAD;

    float qv;
    if (d < D_NOPE) qv = qrow[d];
    else {
        int p = pos[s];
        const float* cr = cosT + (size_t)p * D_ROPE;
        const float* sr = sinT + (size_t)p * D_ROPE;
        const float* t  = qrow + D_NOPE;
        int i = d - D_NOPE;
        if (i < 32) qv = t[2 * i] * cr[i] - t[2 * i + 1] * sr[i];
        else { int i2 = i - 32; qv = t[2 * i2 + 1] * cr[i] + t[2 * i2] * sr[i]; }
    }
    float kvv = (d < D_NOPE) ? kvrow[d] : kpe[(size_t)s * D_ROPE + (d - D_NOPE)];
    int pd = perm8(d);
    Q[off + pd] = tf32r(qv);
    K[off + pd] = tf32r(kvv);
    if (d < D_V) V[((size_t)h * S_ + s) * D_V + d] = tf32r(kvrow[D_NOPE + d]);
}

// ---------------- fused flash attention ----------------
// CTA: 64 q rows of one head. KV streamed in 32-key tiles, cp.async double-buffered.
#define QS_STR 196
#define KS_STR 196
#define VS_STR 132
#define PS_STR 36
#define QS_OFF 0
#define KS_OFF 50176              // 64*196*4
#define KS_BYTES 25088            // 32*196*4
#define VS_OFF (KS_OFF + 2*KS_BYTES)
#define VS_BYTES 16896            // 32*132*4
#define PS_OFF (VS_OFF + 2*VS_BYTES)
#define M_OFF  (PS_OFF + 64*PS_STR*4)
#define L_OFF  (M_OFF + 256)
#define AL_OFF (L_OFF + 256)
#define FLASH_SMEM (AL_OFF + 256)

__global__ __launch_bounds__(256, 1)
void flash_kernel(const float* __restrict__ Q, const float* __restrict__ K,
                  const float* __restrict__ V, float* __restrict__ attn)
{
    const int qt = blockIdx.x;
    const int h  = blockIdx.y;
    const int q0 = qt * 64;
    const int nt = 2 * qt + 2;

    extern __shared__ char sm[];
    const uint32_t sb = smem_u32(sm);
    float* mP = reinterpret_cast<float*>(sm + M_OFF);
    float* lP = reinterpret_cast<float*>(sm + L_OFF);
    float* aP = reinterpret_cast<float*>(sm + AL_OFF);

    const int tid = threadIdx.x;
    const int wid = tid >> 5;
    const int lid = tid & 31;
    const int gl  = lid >> 2;   // groupID 0..7
    const int tg  = lid & 3;    // threadID_in_group 0..3
    const int wm  = wid >> 2;   // 0..1
    const int wn  = wid & 3;    // 0..3

    const float* Qg = Q + ((size_t)h * S_ + q0) * QHEAD;
    const float* Kg = K + (size_t)h * S_ * QHEAD;
    const float* Vg = V + (size_t)h * S_ * D_V;

    auto issueKV = [&](int t, int st) {
        const float* kp = Kg + (size_t)t * 32 * QHEAD;
        uint32_t kd = sb + KS_OFF + st * KS_BYTES;
        #pragma unroll
        for (int i = 0; i < 6; i++) {
            int idx = i * 256 + tid;
            int r = idx / 48, c = idx % 48;
            cp16(kd + r * (KS_STR * 4) + c * 16, kp + (size_t)r * QHEAD + c * 4);
        }
        const float* vp = Vg + (size_t)t * 32 * D_V;
        uint32_t vd = sb + VS_OFF + st * VS_BYTES;
        #pragma unroll
        for (int i = 0; i < 4; i++) {
            int idx = i * 256 + tid;
            int r = idx >> 5, c = idx & 31;
            cp16(vd + r * (VS_STR * 4) + c * 16, vp + (size_t)r * D_V + c * 4);
        }
    };

    // Q tile load (stays resident) + first KV tile, one cp.async group
    #pragma unroll
    for (int i = 0; i < 12; i++) {
        int idx = i * 256 + tid;
        int r = idx / 48, c = idx % 48;
        cp16(sb + QS_OFF + r * (QS_STR * 4) + c * 16, Qg + (size_t)r * QHEAD + c * 4);
    }
    issueKV(0, 0);
    cp_commit();

    if (tid < 64) { mP[tid] = -1e30f; lP[tid] = 0.f; }

    float oacc[2][4][4];
    #pragma unroll
    for (int a = 0; a < 2; a++)
        #pragma unroll
        for (int b = 0; b < 4; b++)
            #pragma unroll
            for (int c = 0; c < 4; c++) oacc[a][b][c] = 0.f;

    const char* QsB = sm + QS_OFF;
    char* PsB = sm + PS_OFF;

    for (int t = 0; t < nt; t++) {
        const int st = t & 1;
        if (t + 1 < nt) { issueKV(t + 1, st ^ 1); cp_commit(); cp_wait<1>(); }
        else            { cp_wait<0>(); }
        __syncthreads();

        // ---- S = Q K^T (64x32 tile; warp: 32 rows x 8 cols) ----
        const char* KsB = sm + KS_OFF + st * KS_BYTES;
        float sacc[2][4] = {{0.f,0.f,0.f,0.f},{0.f,0.f,0.f,0.f}};
        const int bRow = wn * 8 + gl;          // key index (natural)
        #pragma unroll 4
        for (int k0 = 0; k0 < 24; k0++) {
            uint2 bb = *reinterpret_cast<const uint2*>(
                KsB + (bRow * KS_STR + k0 * 8 + 2 * tg) * 4);
            #pragma unroll
            for (int mf = 0; mf < 2; mf++) {
                int r0 = wm * 32 + mf * 16 + gl;
                uint2 lo = *reinterpret_cast<const uint2*>(
                    QsB + (r0 * QS_STR + k0 * 8 + 2 * tg) * 4);
                uint2 hi = *reinterpret_cast<const uint2*>(
                    QsB + ((r0 + 8) * QS_STR + k0 * 8 + 2 * tg) * 4);
                mma8(sacc[mf], lo.x, hi.x, lo.y, hi.y, bb.x, bb.y);
            }
        }
        // store S (natural key cols)
        #pragma unroll
        for (int mf = 0; mf < 2; mf++) {
            int r0 = wm * 32 + mf * 16 + gl;
            int c0 = wn * 8 + 2 * tg;
            *reinterpret_cast<float2*>(PsB + (r0 * PS_STR + c0) * 4) =
                make_float2(sacc[mf][0], sacc[mf][1]);
            *reinterpret_cast<float2*>(PsB + ((r0 + 8) * PS_STR + c0) * 4) =
                make_float2(sacc[mf][2], sacc[mf][3]);
        }
        __syncthreads();

        // ---- online softmax (4 threads / row, 8 keys each) ----
        {
            const int row = tid >> 2;
            const int cb  = (tid & 3) * 8;
            float* prow = reinterpret_cast<float*>(PsB) + row * PS_STR + cb;
            float4 v0 = *reinterpret_cast<float4*>(prow);
            float4 v1 = *reinterpret_cast<float4*>(prow + 4);
            float v[8] = {v0.x, v0.y, v0.z, v0.w, v1.x, v1.y, v1.z, v1.w};
            const int rg = q0 + row;
            const int key0 = t * 32 + cb;
            const bool msk = (t >= 2 * qt);
            float mx = -1e30f;
            #pragma unroll
            for (int j = 0; j < 8; j++) {
                float val = v[j] * SCALE_;
                if (msk && (key0 + j) > rg) val = -1e30f;
                v[j] = val;
                mx = fmaxf(mx, val);
            }
            mx = fmaxf(mx, __shfl_xor_sync(0xffffffffu, mx, 1));
            mx = fmaxf(mx, __shfl_xor_sync(0xffffffffu, mx, 2));
            float mold = mP[row];
            float mnew = fmaxf(mold, mx);
            float al = __expf(mold - mnew);
            float sum = 0.f;
            #pragma unroll
            for (int j = 0; j < 8; j++) {
                float p = __expf(v[j] - mnew);
                sum += p;
                prow[perm8(j)] = tf32r(p);   // key-permuted P store
            }
            sum += __shfl_xor_sync(0xffffffffu, sum, 1);
            sum += __shfl_xor_sync(0xffffffffu, sum, 2);
            if ((tid & 3) == 0) {
                mP[row] = mnew;
                lP[row] = lP[row] * al + sum;
                aP[row] = al;
            }
        }
        __syncthreads();

        // ---- rescale O, then O += P V ----
        const char* VsB = sm + VS_OFF + st * VS_BYTES;
        #pragma unroll
        for (int mf = 0; mf < 2; mf++) {
            int r0 = wm * 32 + mf * 16 + gl;
            float a0 = aP[r0], a8 = aP[r0 + 8];
            #pragma unroll
            for (int nf = 0; nf < 4; nf++) {
                oacc[mf][nf][0] *= a0; oacc[mf][nf][1] *= a0;
                oacc[mf][nf][2] *= a8; oacc[mf][nf][3] *= a8;
            }
        }
        #pragma unroll
        for (int k0 = 0; k0 < 4; k0++) {
            uint2 alo[2], ahi[2];
            #pragma unroll
            for (int mf = 0; mf < 2; mf++) {
                int r0 = wm * 32 + mf * 16 + gl;
                alo[mf] = *reinterpret_cast<const uint2*>(
                    PsB + (r0 * PS_STR + k0 * 8 + 2 * tg) * 4);
                ahi[mf] = *reinterpret_cast<const uint2*>(
                    PsB + ((r0 + 8) * PS_STR + k0 * 8 + 2 * tg) * 4);
            }
            #pragma unroll
            for (int nf = 0; nf < 4; nf++) {
                int nc = wn * 32 + nf * 8 + gl;
                uint32_t b0 = *reinterpret_cast<const uint32_t*>(
                    VsB + ((k0 * 8 + tg) * VS_STR + nc) * 4);
                uint32_t b1 = *reinterpret_cast<const uint32_t*>(
                    VsB + ((k0 * 8 + tg + 4) * VS_STR + nc) * 4);
                #pragma unroll
                for (int mf = 0; mf < 2; mf++)
                    mma8(oacc[mf][nf], alo[mf].x, ahi[mf].x, alo[mf].y, ahi[mf].y, b0, b1);
            }
        }
        __syncthreads();
    }

    // ---- epilogue: O / l -> attn ----
    #pragma unroll
    for (int mf = 0; mf < 2; mf++) {
        int r0 = wm * 32 + mf * 16 + gl;
        float inv0 = 1.f / lP[r0];
        float inv8 = 1.f / lP[r0 + 8];
        #pragma unroll
        for (int nf = 0; nf < 4; nf++) {
            int col = h * D_V + wn * 32 + nf * 8 + 2 * tg;
            float* o0 = attn + (size_t)(q0 + r0) * (H_ * D_V) + col;
            float* o8 = attn + (size_t)(q0 + r0 + 8) * (H_ * D_V) + col;
            *reinterpret_cast<float2*>(o0) = make_float2(oacc[mf][nf][0] * inv0,
                                                         oacc[mf][nf][1] * inv0);
            *reinterpret_cast<float2*>(o8) = make_float2(oacc[mf][nf][2] * inv8,
                                                         oacc[mf][nf][3] * inv8);
        }
    }
}

// ---------------- host launch ----------------
extern "C" void kernel_launch(void* const* d_in, const int* in_sizes, int n_in,
                              void* d_out, int out_size)
{
    const float* x       = (const float*)d_in[0];
    const int*   pos     = (const int*)  d_in[2];
    const float* cosT    = (const float*)d_in[3];
    const float* sinT    = (const float*)d_in[4];
    const float* q_a_w   = (const float*)d_in[5];
    const float* q_a_ln  = (const float*)d_in[6];
    const float* q_b_w   = (const float*)d_in[7];
    const float* kv_a_w  = (const float*)d_in[8];
    const float* kv_a_ln = (const float*)d_in[9];
    const float* kv_b_w  = (const float*)d_in[10];
    const float* o_w     = (const float*)d_in[11];
    float* out = (float*)d_out;
    float* out_cache = out + (size_t)S_ * HID_;

    float *qa, *qn, *ckv, *cnorm, *kpe, *q, *kv, *Q, *K, *V, *attn;
    cudaGetSymbolAddress((void**)&qa,     g_qa);
    cudaGetSymbolAddress((void**)&qn,     g_qn);
    cudaGetSymbolAddress((void**)&ckv,    g_ckv);
    cudaGetSymbolAddress((void**)&cnorm,  g_cnorm);
    cudaGetSymbolAddress((void**)&kpe,    g_kpe);
    cudaGetSymbolAddress((void**)&q,      g_q);
    cudaGetSymbolAddress((void**)&kv,     g_kv);
    cudaGetSymbolAddress((void**)&Q,      g_Q);
    cudaGetSymbolAddress((void**)&K,      g_K);
    cudaGetSymbolAddress((void**)&V,      g_V);
    cudaGetSymbolAddress((void**)&attn,   g_attn);

    cudaFuncSetAttribute(wgemm_kernel, cudaFuncAttributeMaxDynamicSharedMemorySize, SMEM_REQ);
    cudaFuncSetAttribute(flash_kernel, cudaFuncAttributeMaxDynamicSharedMemorySize, FLASH_SMEM);

    dim3 blk(256);

    // 1) q_a = x @ q_a_w
    wgemm_kernel<<<dim3(QL_/128, S_/128), blk, SMEM_REQ>>>(x, HID_, q_a_w, QL_, qa, QL_, QL_, HID_);
    // 2) ckv = x @ kv_a_w
    wgemm_kernel<<<dim3((CKV_W+127)/128, S_/128), blk, SMEM_REQ>>>(x, HID_, kv_a_w, CKV_W, ckv, CKV_W, CKV_W, HID_);
    // 3) RMSNorm q_a
    rms_q_kernel<<<S_, blk>>>(qa, q_a_ln, qn);
    // 4) RMSNorm ckv + RoPE k_pe + kv_cache
    rms_ckv_kernel<<<S_, blk>>>(ckv, kv_a_ln, cosT, sinT, pos, cnorm, kpe, out_cache);
    // 5) q = qn @ q_b_w
    wgemm_kernel<<<dim3(QDIM/128, S_/128), blk, SMEM_REQ>>>(qn, QL_, q_b_w, QDIM, q, QDIM, QDIM, QL_);
    // 6) kv = cnorm @ kv_b_w
    wgemm_kernel<<<dim3(KVDIM/128, S_/128), blk, SMEM_REQ>>>(cnorm, KVL_, kv_b_w, KVDIM, kv, KVDIM, KVDIM, KVL_);
    // 7) assemble (tf32 + perm)
    assemble_kernel<<<dim3(S_, H_), dim3(QHEAD)>>>(q, kv, kpe, cosT, sinT, pos, Q, K, V);
    // 8) fused flash attention
    flash_kernel<<<dim3(S_/64, H_), blk, FLASH_SMEM>>>(Q, K, V, attn);
    // 9) out = attn @ o_w
    wgemm_kernel<<<dim3(HID_/128, S_/128), blk, SMEM_REQ>>>(attn, H_*D_V, o_w, HID_, out, HID_, HID_, H_*D_V);
}

// round 5
// speedup vs baseline: 2.0164x; 1.0980x over previous
#include <cuda_runtime.h>
#include <cuda_bf16.h>
#include <mma.h>
#include <math.h>
#include <stdint.h>

using namespace nvcuda;

// ---------------- problem constants ----------------
#define S_      2048
#define HID_    2048
#define H_      16
#define D_NOPE  128
#define D_ROPE  64
#define D_V     128
#define QHEAD   192
#define QL_     1536
#define KVL_    512
#define CKV_W   576
#define KVA_PAD 768
#define QDIM    3072
#define KVDIM   4096
#define EPS_    1e-6f
#define SCALE_  0.07216878364870322f

// ---------------- scratch ----------------
__device__ float g_x     [S_ * HID_];        // tf32 x
__device__ float g_wqa   [HID_ * QL_];       // tf32 weights
__device__ float g_wqb   [QL_ * QDIM];
__device__ float g_wkva  [HID_ * KVA_PAD];   // tf32, zero-padded 576->768
__device__ float g_wkvb  [KVL_ * KVDIM];
__device__ float g_wo    [H_ * D_V * HID_];
__device__ float g_qa    [S_ * QL_];
__device__ float g_qn    [S_ * QL_];         // tf32
__device__ float g_ckv   [S_ * CKV_W];
__device__ float g_cnorm [S_ * KVL_];        // tf32
__device__ float g_kpe   [S_ * D_ROPE];
__device__ float g_q     [S_ * QDIM];
__device__ float g_kv    [S_ * KVDIM];
__device__ float g_Q     [H_ * S_ * QHEAD];  // tf32, dim-permuted
__device__ float g_K     [H_ * S_ * QHEAD];
__device__ float g_V     [H_ * S_ * D_V];
__device__ float g_attn  [S_ * (H_ * D_V)];  // tf32

__device__ __forceinline__ float tf32r(float f) {
    uint32_t r; asm("cvt.rna.tf32.f32 %0, %1;" : "=r"(r) : "f"(f));
    return __uint_as_float(r);
}
__device__ __forceinline__ int perm8(int c) {
    return (c & ~7) | ((c & 3) << 1) | ((c >> 2) & 1);
}
__device__ __forceinline__ uint32_t smem_u32(const void* p) {
    uint32_t a;
    asm("{ .reg .u64 t; cvta.to.shared.u64 t, %1; cvt.u32.u64 %0, t; }" : "=r"(a) : "l"(p));
    return a;
}
__device__ __forceinline__ void cp16(uint32_t d, const void* s) {
    asm volatile("cp.async.ca.shared.global [%0], [%1], 16;" :: "r"(d), "l"(s));
}
__device__ __forceinline__ void cp_commit() {
    asm volatile("cp.async.commit_group;" ::: "memory");
}
template<int N> __device__ __forceinline__ void cp_wait() {
    asm volatile("cp.async.wait_group %0;" :: "n"(N) : "memory");
}
__device__ __forceinline__ void mma8(float* c, uint32_t a0, uint32_t a1, uint32_t a2, uint32_t a3,
                                     uint32_t b0, uint32_t b1) {
    asm volatile(
        "mma.sync.aligned.m16n8k8.row.col.f32.tf32.tf32.f32 "
        "{%0,%1,%2,%3}, {%4,%5,%6,%7}, {%8,%9}, {%0,%1,%2,%3};"
        : "+f"(c[0]), "+f"(c[1]), "+f"(c[2]), "+f"(c[3])
        : "r"(a0), "r"(a1), "r"(a2), "r"(a3), "r"(b0), "r"(b1));
}

// ---------------- prep: tf32 conversion ----------------
__global__ void conv4_kernel(const float4* __restrict__ src, float4* __restrict__ dst, int n4)
{
    int i = blockIdx.x * blockDim.x + threadIdx.x;
    if (i < n4) {
        float4 v = src[i];
        dst[i] = make_float4(tf32r(v.x), tf32r(v.y), tf32r(v.z), tf32r(v.w));
    }
}
__global__ void pad_kva_kernel(const float* __restrict__ src, float* __restrict__ dst)
{
    int i = blockIdx.x * blockDim.x + threadIdx.x;
    if (i < HID_ * KVA_PAD) {
        int k = i / KVA_PAD, n = i % KVA_PAD;
        dst[i] = (n < CKV_W) ? tf32r(src[k * CKV_W + n]) : 0.f;
    }
}

// ---------------- pipelined wmma tf32 GEMM (operands pre-tf32) ----------------
// BM=128, BN=256, BK=32, 512 threads, 3-stage cp.async
#define A_STRP 36
#define B_STRP 260
#define A_SBYT (128 * A_STRP * 4)   // 18432
#define B_SBYT (32 * B_STRP * 4)    // 33280
#define STG_P  (A_SBYT + B_SBYT)    // 51712
#define SMEM_P (3 * STG_P)          // 155136

__global__ __launch_bounds__(512, 1)
void pgemm_kernel(const float* __restrict__ A, int lda,
                  const float* __restrict__ B, int ldb,
                  float* __restrict__ C, int ldc, int N, int nt1,
                  const float* __restrict__ B2, int ldb2,
                  float* __restrict__ C2, int ldc2, int N2,
                  int K)
{
    int bx = blockIdx.x;
    if (bx >= nt1) { B = B2; ldb = ldb2; C = C2; ldc = ldc2; N = N2; bx -= nt1; }
    const int row0 = blockIdx.y * 128;
    const int col0 = bx * 256;
    const int nk = K / 32;

    extern __shared__ char smem[];
    const uint32_t sb = smem_u32(smem);
    const int tid = threadIdx.x;
    const int wid = tid >> 5;
    const int wm  = wid >> 3;     // 0..1 -> rows wm*64
    const int wn  = wid & 7;      // 0..7 -> cols wn*32

    auto issue = [&](int t) {
        const int s = t % 3;
        const int k0 = t * 32;
        uint32_t ab = sb + s * STG_P;
        #pragma unroll
        for (int i = 0; i < 2; i++) {
            int idx = i * 512 + tid;
            int r = idx >> 3, c = idx & 7;
            cp16(ab + r * (A_STRP * 4) + c * 16, A + (size_t)(row0 + r) * lda + k0 + c * 4);
        }
        uint32_t bb = sb + s * STG_P + A_SBYT;
        #pragma unroll
        for (int i = 0; i < 4; i++) {
            int idx = i * 512 + tid;
            int kr = idx >> 6, c = idx & 63;
            cp16(bb + kr * (B_STRP * 4) + c * 16, B + (size_t)(k0 + kr) * ldb + col0 + c * 4);
        }
    };

    typedef wmma::fragment<wmma::matrix_a, 16, 16, 8, wmma::precision::tf32, wmma::row_major> AFrag;
    typedef wmma::fragment<wmma::matrix_b, 16, 16, 8, wmma::precision::tf32, wmma::row_major> BFrag;
    wmma::fragment<wmma::accumulator, 16, 16, 8, float> acc[4][2];
    #pragma unroll
    for (int i = 0; i < 4; i++)
        #pragma unroll
        for (int j = 0; j < 2; j++) wmma::fill_fragment(acc[i][j], 0.0f);

    issue(0); cp_commit();
    if (nk > 1) { issue(1); cp_commit(); }

    for (int t = 0; t < nk; t++) {
        if (t + 1 < nk) cp_wait<1>(); else cp_wait<0>();
        __syncthreads();
        if (t + 2 < nk) { issue(t + 2); cp_commit(); }

        const float* As = reinterpret_cast<const float*>(smem + (t % 3) * STG_P);
        const float* Bs = reinterpret_cast<const float*>(smem + (t % 3) * STG_P + A_SBYT);

        #pragma unroll
        for (int kk = 0; kk < 4; kk++) {
            AFrag af[4];
            BFrag bf[2];
            #pragma unroll
            for (int mf = 0; mf < 4; mf++)
                wmma::load_matrix_sync(af[mf], As + (wm * 64 + mf * 16) * A_STRP + kk * 8, A_STRP);
            #pragma unroll
            for (int nf = 0; nf < 2; nf++)
                wmma::load_matrix_sync(bf[nf], Bs + (kk * 8) * B_STRP + wn * 32 + nf * 16, B_STRP);
            #pragma unroll
            for (int mf = 0; mf < 4; mf++)
                #pragma unroll
                for (int nf = 0; nf < 2; nf++)
                    wmma::mma_sync(acc[mf][nf], af[mf], bf[nf], acc[mf][nf]);
        }
        __syncthreads();
    }

    #pragma unroll
    for (int mf = 0; mf < 4; mf++) {
        int gr = row0 + wm * 64 + mf * 16;
        #pragma unroll
        for (int nf = 0; nf < 2; nf++) {
            int gc = col0 + wn * 32 + nf * 16;
            if (gc + 16 <= N)
                wmma::store_matrix_sync(C + (size_t)gr * ldc + gc, acc[mf][nf], ldc,
                                        wmma::mem_row_major);
        }
    }
}

// ---------------- RMSNorm q_a (emits tf32) ----------------
__global__ __launch_bounds__(256)
void rms_q_kernel(const float* __restrict__ in, const float* __restrict__ w,
                  float* __restrict__ out)
{
    const int s = blockIdx.x;
    const float* x = in + (size_t)s * QL_;
    float*       y = out + (size_t)s * QL_;
    const int tid = threadIdx.x;

    float v[6];
    float local = 0.f;
    #pragma unroll
    for (int i = 0; i < 6; i++) { int c = tid + i * 256; v[i] = x[c]; local += v[i] * v[i]; }
    __shared__ float sred[256];
    sred[tid] = local; __syncthreads();
    for (int st = 128; st > 0; st >>= 1) {
        if (tid < st) sred[tid] += sred[tid + st];
        __syncthreads();
    }
    float scale = rsqrtf(sred[0] / (float)QL_ + EPS_);
    #pragma unroll
    for (int i = 0; i < 6; i++) { int c = tid + i * 256; y[c] = tf32r(v[i] * scale * w[c]); }
}

// ---------------- RMSNorm ckv (cnorm tf32, cache fp32) + RoPE k_pe ----------------
__global__ __launch_bounds__(256)
void rms_ckv_kernel(const float* __restrict__ ckv, const float* __restrict__ w,
                    const float* __restrict__ cosT, const float* __restrict__ sinT,
                    const int* __restrict__ pos,
                    float* __restrict__ cnorm, float* __restrict__ kpe,
                    float* __restrict__ cache)
{
    const int s = blockIdx.x;
    const float* x = ckv + (size_t)s * CKV_W;
    const int tid = threadIdx.x;

    float v[2];
    float local = 0.f;
    #pragma unroll
    for (int i = 0; i < 2; i++) { int c = tid + i * 256; v[i] = x[c]; local += v[i] * v[i]; }
    __shared__ float sred[256];
    sred[tid] = local; __syncthreads();
    for (int st = 128; st > 0; st >>= 1) {
        if (tid < st) sred[tid] += sred[tid + st];
        __syncthreads();
    }
    float scale = rsqrtf(sred[0] / (float)KVL_ + EPS_);
    #pragma unroll
    for (int i = 0; i < 2; i++) {
        int c = tid + i * 256;
        float y = v[i] * scale * w[c];
        cnorm[(size_t)s * KVL_ + c] = tf32r(y);
        cache[(size_t)s * CKV_W + c] = y;
    }
    if (tid < D_ROPE) {
        int p = pos[s];
        const float* cr = cosT + (size_t)p * D_ROPE;
        const float* sr = sinT + (size_t)p * D_ROPE;
        const float* t  = x + KVL_;
        int i = tid;
        float val;
        if (i < 32) val = t[2 * i] * cr[i] - t[2 * i + 1] * sr[i];
        else { int i2 = i - 32; val = t[2 * i2 + 1] * cr[i] + t[2 * i2] * sr[i]; }
        kpe[(size_t)s * D_ROPE + i] = val;
        cache[(size_t)s * CKV_W + KVL_ + i] = val;
    }
}

// ---------------- assemble Q/K (tf32, perm), V (tf32) ----------------
__global__ void assemble_kernel(const float* __restrict__ q, const float* __restrict__ kv,
                                const float* __restrict__ kpe,
                                const float* __restrict__ cosT, const float* __restrict__ sinT,
                                const int* __restrict__ pos,
                                float* __restrict__ Q, float* __restrict__ K,
                                float* __restrict__ V)
{
    const int s = blockIdx.x;
    const int h = blockIdx.y;
    const int d = threadIdx.x;
    const float* qrow  = q  + (size_t)s * QDIM  + h * QHEAD;
    const float* kvrow = kv + (size_t)s * KVDIM + h * (D_NOPE + D_V);
    const size_t off = ((size_t)h * S_ + s) * QHEAD;

    float qv;
    if (d < D_NOPE) qv = qrow[d];
    else {
        int p = pos[s];
        const float* cr = cosT + (size_t)p * D_ROPE;
        const float* sr = sinT + (size_t)p * D_ROPE;
        const float* t  = qrow + D_NOPE;
        int i = d - D_NOPE;
        if (i < 32) qv = t[2 * i] * cr[i] - t[2 * i + 1] * sr[i];
        else { int i2 = i - 32; qv = t[2 * i2 + 1] * cr[i] + t[2 * i2] * sr[i]; }
    }
    float kvv = (d < D_NOPE) ? kvrow[d] : kpe[(size_t)s * D_ROPE + (d - D_NOPE)];
    int pd = perm8(d);
    Q[off + pd] = tf32r(qv);
    K[off + pd] = tf32r(kvv);
    if (d < D_V) V[((size_t)h * S_ + s) * D_V + d] = tf32r(kvrow[D_NOPE + d]);
}

// ---------------- fused flash attention ----------------
#define QS_STR 196
#define KS_STR 196
#define VS_STR 132
#define PS_STR 36
#define QS_OFF 0
#define KS_OFF 50176
#define KS_BYTES 25088
#define VS_OFF (KS_OFF + 2*KS_BYTES)
#define VS_BYTES 16896
#define PS_OFF (VS_OFF + 2*VS_BYTES)
#define M_OFF  (PS_OFF + 64*PS_STR*4)
#define L_OFF  (M_OFF + 256)
#define AL_OFF (L_OFF + 256)
#define FLASH_SMEM (AL_OFF + 256)

__global__ __launch_bounds__(256, 1)
void flash_kernel(const float* __restrict__ Q, const float* __restrict__ K,
                  const float* __restrict__ V, float* __restrict__ attn)
{
    const int qt = blockIdx.x;
    const int h  = blockIdx.y;
    const int q0 = qt * 64;
    const int nt = 2 * qt + 2;

    extern __shared__ char sm[];
    const uint32_t sb = smem_u32(sm);
    float* mP = reinterpret_cast<float*>(sm + M_OFF);
    float* lP = reinterpret_cast<float*>(sm + L_OFF);
    float* aP = reinterpret_cast<float*>(sm + AL_OFF);

    const int tid = threadIdx.x;
    const int wid = tid >> 5;
    const int lid = tid & 31;
    const int gl  = lid >> 2;
    const int tg  = lid & 3;
    const int wm  = wid >> 2;
    const int wn  = wid & 3;

    const float* Qg = Q + ((size_t)h * S_ + q0) * QHEAD;
    const float* Kg = K + (size_t)h * S_ * QHEAD;
    const float* Vg = V + (size_t)h * S_ * D_V;

    auto issueKV = [&](int t, int st) {
        const float* kp = Kg + (size_t)t * 32 * QHEAD;
        uint32_t kd = sb + KS_OFF + st * KS_BYTES;
        #pragma unroll
        for (int i = 0; i < 6; i++) {
            int idx = i * 256 + tid;
            int r = idx / 48, c = idx % 48;
            cp16(kd + r * (KS_STR * 4) + c * 16, kp + (size_t)r * QHEAD + c * 4);
        }
        const float* vp = Vg + (size_t)t * 32 * D_V;
        uint32_t vd = sb + VS_OFF + st * VS_BYTES;
        #pragma unroll
        for (int i = 0; i < 4; i++) {
            int idx = i * 256 + tid;
            int r = idx >> 5, c = idx & 31;
            cp16(vd + r * (VS_STR * 4) + c * 16, vp + (size_t)r * D_V + c * 4);
        }
    };

    #pragma unroll
    for (int i = 0; i < 12; i++) {
        int idx = i * 256 + tid;
        int r = idx / 48, c = idx % 48;
        cp16(sb + QS_OFF + r * (QS_STR * 4) + c * 16, Qg + (size_t)r * QHEAD + c * 4);
    }
    issueKV(0, 0);
    cp_commit();

    if (tid < 64) { mP[tid] = -1e30f; lP[tid] = 0.f; }

    float oacc[2][4][4];
    #pragma unroll
    for (int a = 0; a < 2; a++)
        #pragma unroll
        for (int b = 0; b < 4; b++)
            #pragma unroll
            for (int c = 0; c < 4; c++) oacc[a][b][c] = 0.f;

    const char* QsB = sm + QS_OFF;
    char* PsB = sm + PS_OFF;

    for (int t = 0; t < nt; t++) {
        const int st = t & 1;
        if (t + 1 < nt) { issueKV(t + 1, st ^ 1); cp_commit(); cp_wait<1>(); }
        else            { cp_wait<0>(); }
        __syncthreads();

        const char* KsB = sm + KS_OFF + st * KS_BYTES;
        float sacc[2][4] = {{0.f,0.f,0.f,0.f},{0.f,0.f,0.f,0.f}};
        const int bRow = wn * 8 + gl;
        #pragma unroll 4
        for (int k0 = 0; k0 < 24; k0++) {
            uint2 bb = *reinterpret_cast<const uint2*>(
                KsB + (bRow * KS_STR + k0 * 8 + 2 * tg) * 4);
            #pragma unroll
            for (int mf = 0; mf < 2; mf++) {
                int r0 = wm * 32 + mf * 16 + gl;
                uint2 lo = *reinterpret_cast<const uint2*>(
                    QsB + (r0 * QS_STR + k0 * 8 + 2 * tg) * 4);
                uint2 hi = *reinterpret_cast<const uint2*>(
                    QsB + ((r0 + 8) * QS_STR + k0 * 8 + 2 * tg) * 4);
                mma8(sacc[mf], lo.x, hi.x, lo.y, hi.y, bb.x, bb.y);
            }
        }
        #pragma unroll
        for (int mf = 0; mf < 2; mf++) {
            int r0 = wm * 32 + mf * 16 + gl;
            int c0 = wn * 8 + 2 * tg;
            *reinterpret_cast<float2*>(PsB + (r0 * PS_STR + c0) * 4) =
                make_float2(sacc[mf][0], sacc[mf][1]);
            *reinterpret_cast<float2*>(PsB + ((r0 + 8) * PS_STR + c0) * 4) =
                make_float2(sacc[mf][2], sacc[mf][3]);
        }
        __syncthreads();

        {
            const int row = tid >> 2;
            const int cb  = (tid & 3) * 8;
            float* prow = reinterpret_cast<float*>(PsB) + row * PS_STR + cb;
            float4 v0 = *reinterpret_cast<float4*>(prow);
            float4 v1 = *reinterpret_cast<float4*>(prow + 4);
            float v[8] = {v0.x, v0.y, v0.z, v0.w, v1.x, v1.y, v1.z, v1.w};
            const int rg = q0 + row;
            const int key0 = t * 32 + cb;
            const bool msk = (t >= 2 * qt);
            float mx = -1e30f;
            #pragma unroll
            for (int j = 0; j < 8; j++) {
                float val = v[j] * SCALE_;
                if (msk && (key0 + j) > rg) val = -1e30f;
                v[j] = val;
                mx = fmaxf(mx, val);
            }
            mx = fmaxf(mx, __shfl_xor_sync(0xffffffffu, mx, 1));
            mx = fmaxf(mx, __shfl_xor_sync(0xffffffffu, mx, 2));
            float mold = mP[row];
            float mnew = fmaxf(mold, mx);
            float al = __expf(mold - mnew);
            float sum = 0.f;
            #pragma unroll
            for (int j = 0; j < 8; j++) {
                float p = __expf(v[j] - mnew);
                sum += p;
                prow[perm8(j)] = tf32r(p);
            }
            sum += __shfl_xor_sync(0xffffffffu, sum, 1);
            sum += __shfl_xor_sync(0xffffffffu, sum, 2);
            if ((tid & 3) == 0) {
                mP[row] = mnew;
                lP[row] = lP[row] * al + sum;
                aP[row] = al;
            }
        }
        __syncthreads();

        const char* VsB = sm + VS_OFF + st * VS_BYTES;
        #pragma unroll
        for (int mf = 0; mf < 2; mf++) {
            int r0 = wm * 32 + mf * 16 + gl;
            float a0 = aP[r0], a8 = aP[r0 + 8];
            #pragma unroll
            for (int nf = 0; nf < 4; nf++) {
                oacc[mf][nf][0] *= a0; oacc[mf][nf][1] *= a0;
                oacc[mf][nf][2] *= a8; oacc[mf][nf][3] *= a8;
            }
        }
        #pragma unroll
        for (int k0 = 0; k0 < 4; k0++) {
            uint2 alo[2], ahi[2];
            #pragma unroll
            for (int mf = 0; mf < 2; mf++) {
                int r0 = wm * 32 + mf * 16 + gl;
                alo[mf] = *reinterpret_cast<const uint2*>(
                    PsB + (r0 * PS_STR + k0 * 8 + 2 * tg) * 4);
                ahi[mf] = *reinterpret_cast<const uint2*>(
                    PsB + ((r0 + 8) * PS_STR + k0 * 8 + 2 * tg) * 4);
            }
            #pragma unroll
            for (int nf = 0; nf < 4; nf++) {
                int nc = wn * 32 + nf * 8 + gl;
                uint32_t b0 = *reinterpret_cast<const uint32_t*>(
                    VsB + ((k0 * 8 + tg) * VS_STR + nc) * 4);
                uint32_t b1 = *reinterpret_cast<const uint32_t*>(
                    VsB + ((k0 * 8 + tg + 4) * VS_STR + nc) * 4);
                #pragma unroll
                for (int mf = 0; mf < 2; mf++)
                    mma8(oacc[mf][nf], alo[mf].x, ahi[mf].x, alo[mf].y, ahi[mf].y, b0, b1);
            }
        }
        __syncthreads();
    }

    #pragma unroll
    for (int mf = 0; mf < 2; mf++) {
        int r0 = wm * 32 + mf * 16 + gl;
        float inv0 = 1.f / lP[r0];
        float inv8 = 1.f / lP[r0 + 8];
        #pragma unroll
        for (int nf = 0; nf < 4; nf++) {
            int col = h * D_V + wn * 32 + nf * 8 + 2 * tg;
            float* o0 = attn + (size_t)(q0 + r0) * (H_ * D_V) + col;
            float* o8 = attn + (size_t)(q0 + r0 + 8) * (H_ * D_V) + col;
            *reinterpret_cast<float2*>(o0) = make_float2(tf32r(oacc[mf][nf][0] * inv0),
                                                         tf32r(oacc[mf][nf][1] * inv0));
            *reinterpret_cast<float2*>(o8) = make_float2(tf32r(oacc[mf][nf][2] * inv8),
                                                         tf32r(oacc[mf][nf][3] * inv8));
        }
    }
}

// ---------------- host launch ----------------
extern "C" void kernel_launch(void* const* d_in, const int* in_sizes, int n_in,
                              void* d_out, int out_size)
{
    const float* x       = (const float*)d_in[0];
    const int*   pos     = (const int*)  d_in[2];
    const float* cosT    = (const float*)d_in[3];
    const float* sinT    = (const float*)d_in[4];
    const float* q_a_w   = (const float*)d_in[5];
    const float* q_a_ln  = (const float*)d_in[6];
    const float* q_b_w   = (const float*)d_in[7];
    const float* kv_a_w  = (const float*)d_in[8];
    const float* kv_a_ln = (const float*)d_in[9];
    const float* kv_b_w  = (const float*)d_in[10];
    const float* o_w     = (const float*)d_in[11];
    float* out = (float*)d_out;
    float* out_cache = out + (size_t)S_ * HID_;

    float *xc, *wqa, *wqb, *wkva, *wkvb, *wo;
    float *qa, *qn, *ckv, *cnorm, *kpe, *q, *kv, *Q, *K, *V, *attn;
    cudaGetSymbolAddress((void**)&xc,     g_x);
    cudaGetSymbolAddress((void**)&wqa,    g_wqa);
    cudaGetSymbolAddress((void**)&wqb,    g_wqb);
    cudaGetSymbolAddress((void**)&wkva,   g_wkva);
    cudaGetSymbolAddress((void**)&wkvb,   g_wkvb);
    cudaGetSymbolAddress((void**)&wo,     g_wo);
    cudaGetSymbolAddress((void**)&qa,     g_qa);
    cudaGetSymbolAddress((void**)&qn,     g_qn);
    cudaGetSymbolAddress((void**)&ckv,    g_ckv);
    cudaGetSymbolAddress((void**)&cnorm,  g_cnorm);
    cudaGetSymbolAddress((void**)&kpe,    g_kpe);
    cudaGetSymbolAddress((void**)&q,      g_q);
    cudaGetSymbolAddress((void**)&kv,     g_kv);
    cudaGetSymbolAddress((void**)&Q,      g_Q);
    cudaGetSymbolAddress((void**)&K,      g_K);
    cudaGetSymbolAddress((void**)&V,      g_V);
    cudaGetSymbolAddress((void**)&attn,   g_attn);

    cudaFuncSetAttribute(pgemm_kernel, cudaFuncAttributeMaxDynamicSharedMemorySize, SMEM_P);
    cudaFuncSetAttribute(flash_kernel, cudaFuncAttributeMaxDynamicSharedMemorySize, FLASH_SMEM);

    // ---- prep: tf32 conversions ----
    auto conv = [&](const float* s, float* d, int n) {
        conv4_kernel<<<(n / 4 + 255) / 256, 256>>>(
            reinterpret_cast<const float4*>(s), reinterpret_cast<float4*>(d), n / 4);
    };
    conv(x, xc, S_ * HID_);
    conv(q_a_w, wqa, HID_ * QL_);
    conv(q_b_w, wqb, QL_ * QDIM);
    conv(kv_b_w, wkvb, KVL_ * KVDIM);
    conv(o_w, wo, H_ * D_V * HID_);
    pad_kva_kernel<<<(HID_ * KVA_PAD + 255) / 256, 256>>>(kv_a_w, wkva);

    dim3 blk5(512);

    // 1+2) fused: qa = x@q_a_w (6 col tiles) ; ckv = x@kv_a_w (3 col tiles, padded)
    pgemm_kernel<<<dim3(9, S_/128), blk5, SMEM_P>>>(
        xc, HID_, wqa, QL_, qa, QL_, QL_, 6,
        wkva, KVA_PAD, ckv, CKV_W, CKV_W, HID_);
    // 3) RMSNorm q_a -> tf32
    rms_q_kernel<<<S_, 256>>>(qa, q_a_ln, qn);
    // 4) RMSNorm ckv -> cnorm(tf32) + RoPE k_pe + kv_cache
    rms_ckv_kernel<<<S_, 256>>>(ckv, kv_a_ln, cosT, sinT, pos, cnorm, kpe, out_cache);
    // 5) q = qn @ q_b_w
    pgemm_kernel<<<dim3(QDIM/256, S_/128), blk5, SMEM_P>>>(
        qn, QL_, wqb, QDIM, q, QDIM, QDIM, QDIM/256,
        nullptr, 0, nullptr, 0, 0, QL_);
    // 6) kv = cnorm @ kv_b_w
    pgemm_kernel<<<dim3(KVDIM/256, S_/128), blk5, SMEM_P>>>(
        cnorm, KVL_, wkvb, KVDIM, kv, KVDIM, KVDIM, KVDIM/256,
        nullptr, 0, nullptr, 0, 0, KVL_);
    // 7) assemble
    assemble_kernel<<<dim3(S_, H_), dim3(QHEAD)>>>(q, kv, kpe, cosT, sinT, pos, Q, K, V);
    // 8) fused flash attention
    flash_kernel<<<dim3(S_/64, H_), 256, FLASH_SMEM>>>(Q, K, V, attn);
    // 9) out = attn @ o_w
    pgemm_kernel<<<dim3(HID_/256, S_/128), blk5, SMEM_P>>>(
        attn, H_*D_V, wo, HID_, out, HID_, HID_, HID_/256,
        nullptr, 0, nullptr, 0, 0, H_*D_V);
}

// round 6
// speedup vs baseline: 4.9986x; 2.4790x over previous
#include <cuda_runtime.h>
#include <cuda_fp16.h>
#include <mma.h>
#include <math.h>
#include <stdint.h>

using namespace nvcuda;

// ---------------- problem constants ----------------
#define S_      2048
#define HID_    2048
#define H_      16
#define D_NOPE  128
#define D_ROPE  64
#define D_V     128
#define QHEAD   192
#define QL_     1536
#define KVL_    512
#define CKV_W   576
#define KVA_PAD 768
#define QDIM    3072
#define KVDIM   4096
#define EPS_    1e-6f
#define SCALE_  0.07216878364870322f

// ---------------- scratch ----------------
__device__ __half g_x     [S_ * HID_];
__device__ __half g_wqa   [HID_ * QL_];
__device__ __half g_wqb   [QL_ * QDIM];
__device__ __half g_wkva  [HID_ * KVA_PAD];   // zero-padded 576->768
__device__ __half g_wkvb  [KVL_ * KVDIM];
__device__ __half g_wo    [H_ * D_V * HID_];
__device__ float  g_qa    [S_ * QL_];
__device__ __half g_qn    [S_ * QL_];
__device__ float  g_ckv   [S_ * CKV_W];
__device__ __half g_cnorm [S_ * KVL_];
__device__ float  g_kpe   [S_ * D_ROPE];
__device__ float  g_q     [S_ * QDIM];
__device__ float  g_kv    [S_ * KVDIM];
__device__ __half g_Q     [H_ * S_ * QHEAD];  // k-dim perm16
__device__ __half g_K     [H_ * S_ * QHEAD];  // k-dim perm16
__device__ __half g_V     [H_ * D_V * S_];    // per-head transposed [h][d][s], s perm16
__device__ __half g_attn  [S_ * (H_ * D_V)];

__device__ __forceinline__ int perm16(int c) {
    int j = c & 15;
    return (c & ~15) | (((j >> 1) & 3) << 2) | ((j >> 3) << 1) | (j & 1);
}
__device__ __forceinline__ uint32_t smem_u32(const void* p) {
    uint32_t a;
    asm("{ .reg .u64 t; cvta.to.shared.u64 t, %1; cvt.u32.u64 %0, t; }" : "=r"(a) : "l"(p));
    return a;
}
__device__ __forceinline__ void cp16(uint32_t d, const void* s) {
    asm volatile("cp.async.ca.shared.global [%0], [%1], 16;" :: "r"(d), "l"(s));
}
__device__ __forceinline__ void cp_commit() {
    asm volatile("cp.async.commit_group;" ::: "memory");
}
template<int N> __device__ __forceinline__ void cp_wait() {
    asm volatile("cp.async.wait_group %0;" :: "n"(N) : "memory");
}
// m16n8k16 fp16 mma, fp32 accum
__device__ __forceinline__ void mma16(float* c, uint32_t a0, uint32_t a1, uint32_t a2, uint32_t a3,
                                      uint32_t b0, uint32_t b1) {
    asm volatile(
        "mma.sync.aligned.m16n8k16.row.col.f32.f16.f16.f32 "
        "{%0,%1,%2,%3}, {%4,%5,%6,%7}, {%8,%9}, {%0,%1,%2,%3};"
        : "+f"(c[0]), "+f"(c[1]), "+f"(c[2]), "+f"(c[3])
        : "r"(a0), "r"(a1), "r"(a2), "r"(a3), "r"(b0), "r"(b1));
}

// ---------------- prep: fp16 conversion ----------------
__global__ void conv_h_kernel(const float4* __restrict__ src, __half2* __restrict__ dst, int n4)
{
    int i = blockIdx.x * blockDim.x + threadIdx.x;
    if (i < n4) {
        float4 v = src[i];
        dst[2 * i + 0] = __floats2half2_rn(v.x, v.y);
        dst[2 * i + 1] = __floats2half2_rn(v.z, v.w);
    }
}
__global__ void pad_kva_kernel(const float* __restrict__ src, __half* __restrict__ dst)
{
    int i = blockIdx.x * blockDim.x + threadIdx.x;
    if (i < HID_ * KVA_PAD) {
        int k = i / KVA_PAD, n = i % KVA_PAD;
        dst[i] = (n < CKV_W) ? __float2half(src[k * CKV_W + n]) : __half(0.f);
    }
}

// ---------------- pipelined fp16 GEMM ----------------
// BM=128, BN=256, BK=32, 512 threads, 3-stage cp.async
#define A_STRH 40     // halfs: 32 + 8 pad (80B row)
#define B_STRH 264    // halfs: 256 + 8 pad (528B row)
#define A_SBYT (128 * A_STRH * 2)   // 10240
#define B_SBYT (32 * B_STRH * 2)    // 16896
#define STG_P  (A_SBYT + B_SBYT)    // 27136
#define SMEM_P (3 * STG_P)          // 81408

__global__ __launch_bounds__(512, 1)
void pgemm_kernel(const __half* __restrict__ A, int lda,
                  const __half* __restrict__ B, int ldb,
                  float* __restrict__ C, int ldc, int N, int nt1,
                  const __half* __restrict__ B2, int ldb2,
                  float* __restrict__ C2, int ldc2, int N2,
                  int K)
{
    int bx = blockIdx.x;
    if (bx >= nt1) { B = B2; ldb = ldb2; C = C2; ldc = ldc2; N = N2; bx -= nt1; }
    const int row0 = blockIdx.y * 128;
    const int col0 = bx * 256;
    const int nk = K / 32;

    extern __shared__ char smem[];
    const uint32_t sb = smem_u32(smem);
    const int tid = threadIdx.x;
    const int wid = tid >> 5;
    const int wm  = wid >> 3;
    const int wn  = wid & 7;

    auto issue = [&](int t) {
        const int s = t % 3;
        const int k0 = t * 32;
        uint32_t ab = sb + s * STG_P;
        {
            int r = tid >> 2, c = tid & 3;
            cp16(ab + r * (A_STRH * 2) + c * 16, A + (size_t)(row0 + r) * lda + k0 + c * 8);
        }
        uint32_t bb = sb + s * STG_P + A_SBYT;
        #pragma unroll
        for (int i = 0; i < 2; i++) {
            int idx = i * 512 + tid;
            int kr = idx >> 5, c = idx & 31;
            cp16(bb + kr * (B_STRH * 2) + c * 16, B + (size_t)(k0 + kr) * ldb + col0 + c * 8);
        }
    };

    typedef wmma::fragment<wmma::matrix_a, 16, 16, 16, __half, wmma::row_major> AFrag;
    typedef wmma::fragment<wmma::matrix_b, 16, 16, 16, __half, wmma::row_major> BFrag;
    wmma::fragment<wmma::accumulator, 16, 16, 16, float> acc[4][2];
    #pragma unroll
    for (int i = 0; i < 4; i++)
        #pragma unroll
        for (int j = 0; j < 2; j++) wmma::fill_fragment(acc[i][j], 0.0f);

    issue(0); cp_commit();
    if (nk > 1) { issue(1); cp_commit(); }

    for (int t = 0; t < nk; t++) {
        if (t + 1 < nk) cp_wait<1>(); else cp_wait<0>();
        __syncthreads();
        if (t + 2 < nk) { issue(t + 2); cp_commit(); }

        const __half* As = reinterpret_cast<const __half*>(smem + (t % 3) * STG_P);
        const __half* Bs = reinterpret_cast<const __half*>(smem + (t % 3) * STG_P + A_SBYT);

        #pragma unroll
        for (int kk = 0; kk < 2; kk++) {
            AFrag af[4];
            BFrag bf[2];
            #pragma unroll
            for (int mf = 0; mf < 4; mf++)
                wmma::load_matrix_sync(af[mf], As + (wm * 64 + mf * 16) * A_STRH + kk * 16, A_STRH);
            #pragma unroll
            for (int nf = 0; nf < 2; nf++)
                wmma::load_matrix_sync(bf[nf], Bs + (kk * 16) * B_STRH + wn * 32 + nf * 16, B_STRH);
            #pragma unroll
            for (int mf = 0; mf < 4; mf++)
                #pragma unroll
                for (int nf = 0; nf < 2; nf++)
                    wmma::mma_sync(acc[mf][nf], af[mf], bf[nf], acc[mf][nf]);
        }
        __syncthreads();
    }

    #pragma unroll
    for (int mf = 0; mf < 4; mf++) {
        int gr = row0 + wm * 64 + mf * 16;
        #pragma unroll
        for (int nf = 0; nf < 2; nf++) {
            int gc = col0 + wn * 32 + nf * 16;
            if (gc + 16 <= N)
                wmma::store_matrix_sync(C + (size_t)gr * ldc + gc, acc[mf][nf], ldc,
                                        wmma::mem_row_major);
        }
    }
}

// ---------------- RMSNorm q_a (emits fp16) ----------------
__global__ __launch_bounds__(256)
void rms_q_kernel(const float* __restrict__ in, const float* __restrict__ w,
                  __half* __restrict__ out)
{
    const int s = blockIdx.x;
    const float* x = in + (size_t)s * QL_;
    __half*      y = out + (size_t)s * QL_;
    const int tid = threadIdx.x;

    float v[6];
    float local = 0.f;
    #pragma unroll
    for (int i = 0; i < 6; i++) { int c = tid + i * 256; v[i] = x[c]; local += v[i] * v[i]; }
    __shared__ float sred[256];
    sred[tid] = local; __syncthreads();
    for (int st = 128; st > 0; st >>= 1) {
        if (tid < st) sred[tid] += sred[tid + st];
        __syncthreads();
    }
    float scale = rsqrtf(sred[0] / (float)QL_ + EPS_);
    #pragma unroll
    for (int i = 0; i < 6; i++) { int c = tid + i * 256; y[c] = __float2half(v[i] * scale * w[c]); }
}

// ---------------- RMSNorm ckv (cnorm fp16, cache fp32) + RoPE k_pe ----------------
__global__ __launch_bounds__(256)
void rms_ckv_kernel(const float* __restrict__ ckv, const float* __restrict__ w,
                    const float* __restrict__ cosT, const float* __restrict__ sinT,
                    const int* __restrict__ pos,
                    __half* __restrict__ cnorm, float* __restrict__ kpe,
                    float* __restrict__ cache)
{
    const int s = blockIdx.x;
    const float* x = ckv + (size_t)s * CKV_W;
    const int tid = threadIdx.x;

    float v[2];
    float local = 0.f;
    #pragma unroll
    for (int i = 0; i < 2; i++) { int c = tid + i * 256; v[i] = x[c]; local += v[i] * v[i]; }
    __shared__ float sred[256];
    sred[tid] = local; __syncthreads();
    for (int st = 128; st > 0; st >>= 1) {
        if (tid < st) sred[tid] += sred[tid + st];
        __syncthreads();
    }
    float scale = rsqrtf(sred[0] / (float)KVL_ + EPS_);
    #pragma unroll
    for (int i = 0; i < 2; i++) {
        int c = tid + i * 256;
        float y = v[i] * scale * w[c];
        cnorm[(size_t)s * KVL_ + c] = __float2half(y);
        cache[(size_t)s * CKV_W + c] = y;
    }
    if (tid < D_ROPE) {
        int p = pos[s];
        const float* cr = cosT + (size_t)p * D_ROPE;
        const float* sr = sinT + (size_t)p * D_ROPE;
        const float* t  = x + KVL_;
        int i = tid;
        float val;
        if (i < 32) val = t[2 * i] * cr[i] - t[2 * i + 1] * sr[i];
        else { int i2 = i - 32; val = t[2 * i2 + 1] * cr[i] + t[2 * i2] * sr[i]; }
        kpe[(size_t)s * D_ROPE + i] = val;
        cache[(size_t)s * CKV_W + KVL_ + i] = val;
    }
}

// ---------------- assemble Q/K (fp16, k-dim perm16) ----------------
__global__ void assemble_kernel(const float* __restrict__ q, const float* __restrict__ kv,
                                const float* __restrict__ kpe,
                                const float* __restrict__ cosT, const float* __restrict__ sinT,
                                const int* __restrict__ pos,
                                __half* __restrict__ Q, __half* __restrict__ K)
{
    const int s = blockIdx.x;
    const int h = blockIdx.y;
    const int d = threadIdx.x;
    const float* qrow  = q  + (size_t)s * QDIM  + h * QHEAD;
    const float* kvrow = kv + (size_t)s * KVDIM + h * (D_NOPE + D_V);
    const size_t off = ((size_t)h * S_ + s) * QHEAD;

    float qv;
    if (d < D_NOPE) qv = qrow[d];
    else {
        int p = pos[s];
        const float* cr = cosT + (size_t)p * D_ROPE;
        const float* sr = sinT + (size_t)p * D_ROPE;
        const float* t  = qrow + D_NOPE;
        int i = d - D_NOPE;
        if (i < 32) qv = t[2 * i] * cr[i] - t[2 * i + 1] * sr[i];
        else { int i2 = i - 32; qv = t[2 * i2 + 1] * cr[i] + t[2 * i2] * sr[i]; }
    }
    float kvv = (d < D_NOPE) ? kvrow[d] : kpe[(size_t)s * D_ROPE + (d - D_NOPE)];
    int pd = perm16(d);
    Q[off + pd] = __float2half(qv);
    K[off + pd] = __float2half(kvv);
}

// ---------------- V transpose: g_V[h][d][s] fp16, s perm16 ----------------
__global__ __launch_bounds__(256)
void vtrans_kernel(const float* __restrict__ kv, __half* __restrict__ V)
{
    const int s0 = blockIdx.x * 64;
    const int h  = blockIdx.y;
    const int tid = threadIdx.x;
    __shared__ float vt[64 * 133];

    #pragma unroll
    for (int i = 0; i < 32; i++) {
        int idx = i * 256 + tid;
        int sl = idx >> 7, d = idx & 127;
        vt[sl * 133 + d] = kv[(size_t)(s0 + sl) * KVDIM + h * (D_NOPE + D_V) + D_NOPE + d];
    }
    __syncthreads();
    #pragma unroll
    for (int i = 0; i < 32; i++) {
        int idx = i * 256 + tid;
        int d = idx >> 6, sl = idx & 63;
        V[((size_t)h * D_V + d) * S_ + s0 + perm16(sl)] = __float2half(vt[sl * 133 + d]);
    }
}

// ---------------- fused flash attention (fp16) ----------------
#define QS_STR 200   // halfs (400B)
#define KS_STR 200
#define VS_STR 40    // halfs (80B)
#define SF_STR 36    // floats
#define PH_STR 40    // halfs
#define QS_OFF 0
#define KS_OFF 25600
#define KS_BYTES 12800
#define VS_OFF (KS_OFF + 2*KS_BYTES)     // 51200
#define VS_BYTES 10240
#define SF_OFF (VS_OFF + 2*VS_BYTES)     // 71680
#define PH_OFF (SF_OFF + 64*SF_STR*4)    // 80896
#define M_OFF  (PH_OFF + 64*PH_STR*2)    // 86016
#define L_OFF  (M_OFF + 256)
#define AL_OFF (L_OFF + 256)
#define FLASH_SMEM (AL_OFF + 256)

__global__ __launch_bounds__(256, 1)
void flash_kernel(const __half* __restrict__ Q, const __half* __restrict__ K,
                  const __half* __restrict__ V, __half* __restrict__ attn)
{
    const int qt = blockIdx.x;
    const int h  = blockIdx.y;
    const int q0 = qt * 64;
    const int nt = 2 * qt + 2;

    extern __shared__ char sm[];
    const uint32_t sb = smem_u32(sm);
    float* mP = reinterpret_cast<float*>(sm + M_OFF);
    float* lP = reinterpret_cast<float*>(sm + L_OFF);
    float* aP = reinterpret_cast<float*>(sm + AL_OFF);

    const int tid = threadIdx.x;
    const int wid = tid >> 5;
    const int lid = tid & 31;
    const int gl  = lid >> 2;
    const int tg  = lid & 3;
    const int wm  = wid >> 2;
    const int wn  = wid & 3;

    const __half* Qg = Q + ((size_t)h * S_ + q0) * QHEAD;
    const __half* Kg = K + (size_t)h * S_ * QHEAD;
    const __half* Vg = V + (size_t)h * D_V * S_;

    auto issueKV = [&](int t, int st) {
        const __half* kp = Kg + (size_t)t * 32 * QHEAD;
        uint32_t kd = sb + KS_OFF + st * KS_BYTES;
        #pragma unroll
        for (int i = 0; i < 3; i++) {
            int idx = i * 256 + tid;
            int r = idx / 24, c = idx % 24;
            cp16(kd + r * (KS_STR * 2) + c * 16, kp + (size_t)r * QHEAD + c * 8);
        }
        uint32_t vd = sb + VS_OFF + st * VS_BYTES;
        #pragma unroll
        for (int i = 0; i < 2; i++) {
            int idx = i * 256 + tid;
            int d = idx >> 2, c = idx & 3;
            cp16(vd + d * (VS_STR * 2) + c * 16, Vg + (size_t)d * S_ + t * 32 + c * 8);
        }
    };

    // Q tile (resident) + first KV tile
    #pragma unroll
    for (int i = 0; i < 6; i++) {
        int idx = i * 256 + tid;
        int r = idx / 24, c = idx % 24;
        cp16(sb + QS_OFF + r * (QS_STR * 2) + c * 16, Qg + (size_t)r * QHEAD + c * 8);
    }
    issueKV(0, 0);
    cp_commit();

    if (tid < 64) { mP[tid] = -1e30f; lP[tid] = 0.f; }

    float oacc[2][4][4];
    #pragma unroll
    for (int a = 0; a < 2; a++)
        #pragma unroll
        for (int b = 0; b < 4; b++)
            #pragma unroll
            for (int c = 0; c < 4; c++) oacc[a][b][c] = 0.f;

    const char* QsB = sm + QS_OFF;
    char* SfB = sm + SF_OFF;
    char* PhB = sm + PH_OFF;

    for (int t = 0; t < nt; t++) {
        const int st = t & 1;
        if (t + 1 < nt) { issueKV(t + 1, st ^ 1); cp_commit(); cp_wait<1>(); }
        else            { cp_wait<0>(); }
        __syncthreads();

        // ---- S = Q K^T ----
        const char* KsB = sm + KS_OFF + st * KS_BYTES;
        float sacc[2][4] = {{0.f,0.f,0.f,0.f},{0.f,0.f,0.f,0.f}};
        const int bRow = wn * 8 + gl;
        #pragma unroll 4
        for (int kk = 0; kk < 12; kk++) {
            uint2 bb = *reinterpret_cast<const uint2*>(
                KsB + (bRow * KS_STR + kk * 16 + 4 * tg) * 2);
            #pragma unroll
            for (int mf = 0; mf < 2; mf++) {
                int r0 = wm * 32 + mf * 16 + gl;
                uint2 lo = *reinterpret_cast<const uint2*>(
                    QsB + (r0 * QS_STR + kk * 16 + 4 * tg) * 2);
                uint2 hi = *reinterpret_cast<const uint2*>(
                    QsB + ((r0 + 8) * QS_STR + kk * 16 + 4 * tg) * 2);
                mma16(sacc[mf], lo.x, hi.x, lo.y, hi.y, bb.x, bb.y);
            }
        }
        #pragma unroll
        for (int mf = 0; mf < 2; mf++) {
            int r0 = wm * 32 + mf * 16 + gl;
            int c0 = wn * 8 + 2 * tg;
            *reinterpret_cast<float2*>(SfB + (r0 * SF_STR + c0) * 4) =
                make_float2(sacc[mf][0], sacc[mf][1]);
            *reinterpret_cast<float2*>(SfB + ((r0 + 8) * SF_STR + c0) * 4) =
                make_float2(sacc[mf][2], sacc[mf][3]);
        }
        __syncthreads();

        // ---- online softmax ----
        {
            const int row = tid >> 2;
            const int cb  = (tid & 3) * 8;
            float* srow = reinterpret_cast<float*>(SfB) + row * SF_STR + cb;
            __half* prow = reinterpret_cast<__half*>(PhB) + row * PH_STR;
            float4 v0 = *reinterpret_cast<float4*>(srow);
            float4 v1 = *reinterpret_cast<float4*>(srow + 4);
            float v[8] = {v0.x, v0.y, v0.z, v0.w, v1.x, v1.y, v1.z, v1.w};
            const int rg = q0 + row;
            const int key0 = t * 32 + cb;
            const bool msk = (t >= 2 * qt);
            float mx = -1e30f;
            #pragma unroll
            for (int j = 0; j < 8; j++) {
                float val = v[j] * SCALE_;
                if (msk && (key0 + j) > rg) val = -1e30f;
                v[j] = val;
                mx = fmaxf(mx, val);
            }
            mx = fmaxf(mx, __shfl_xor_sync(0xffffffffu, mx, 1));
            mx = fmaxf(mx, __shfl_xor_sync(0xffffffffu, mx, 2));
            float mold = mP[row];
            float mnew = fmaxf(mold, mx);
            float al = __expf(mold - mnew);
            float sum = 0.f;
            #pragma unroll
            for (int j = 0; j < 8; j++) {
                float p = __expf(v[j] - mnew);
                sum += p;
                prow[perm16(cb + j)] = __float2half(p);
            }
            sum += __shfl_xor_sync(0xffffffffu, sum, 1);
            sum += __shfl_xor_sync(0xffffffffu, sum, 2);
            if ((tid & 3) == 0) {
                mP[row] = mnew;
                lP[row] = lP[row] * al + sum;
                aP[row] = al;
            }
        }
        __syncthreads();

        // ---- rescale O, then O += P V ----
        const char* VsB = sm + VS_OFF + st * VS_BYTES;
        #pragma unroll
        for (int mf = 0; mf < 2; mf++) {
            int r0 = wm * 32 + mf * 16 + gl;
            float a0 = aP[r0], a8 = aP[r0 + 8];
            #pragma unroll
            for (int nf = 0; nf < 4; nf++) {
                oacc[mf][nf][0] *= a0; oacc[mf][nf][1] *= a0;
                oacc[mf][nf][2] *= a8; oacc[mf][nf][3] *= a8;
            }
        }
        #pragma unroll
        for (int kk = 0; kk < 2; kk++) {
            uint2 alo[2], ahi[2];
            #pragma unroll
            for (int mf = 0; mf < 2; mf++) {
                int r0 = wm * 32 + mf * 16 + gl;
                alo[mf] = *reinterpret_cast<const uint2*>(
                    PhB + (r0 * PH_STR + kk * 16 + 4 * tg) * 2);
                ahi[mf] = *reinterpret_cast<const uint2*>(
                    PhB + ((r0 + 8) * PH_STR + kk * 16 + 4 * tg) * 2);
            }
            #pragma unroll
            for (int nf = 0; nf < 4; nf++) {
                int nc = wn * 32 + nf * 8 + gl;
                uint2 bv = *reinterpret_cast<const uint2*>(
                    VsB + (nc * VS_STR + kk * 16 + 4 * tg) * 2);
                #pragma unroll
                for (int mf = 0; mf < 2; mf++)
                    mma16(oacc[mf][nf], alo[mf].x, ahi[mf].x, alo[mf].y, ahi[mf].y, bv.x, bv.y);
            }
        }
        __syncthreads();
    }

    // ---- epilogue: O / l -> attn (fp16) ----
    #pragma unroll
    for (int mf = 0; mf < 2; mf++) {
        int r0 = wm * 32 + mf * 16 + gl;
        float inv0 = 1.f / lP[r0];
        float inv8 = 1.f / lP[r0 + 8];
        #pragma unroll
        for (int nf = 0; nf < 4; nf++) {
            int col = h * D_V + wn * 32 + nf * 8 + 2 * tg;
            __half2* o0 = reinterpret_cast<__half2*>(attn + (size_t)(q0 + r0) * (H_ * D_V) + col);
            __half2* o8 = reinterpret_cast<__half2*>(attn + (size_t)(q0 + r0 + 8) * (H_ * D_V) + col);
            *o0 = __floats2half2_rn(oacc[mf][nf][0] * inv0, oacc[mf][nf][1] * inv0);
            *o8 = __floats2half2_rn(oacc[mf][nf][2] * inv8, oacc[mf][nf][3] * inv8);
        }
    }
}

// ---------------- host launch ----------------
extern "C" void kernel_launch(void* const* d_in, const int* in_sizes, int n_in,
                              void* d_out, int out_size)
{
    const float* x       = (const float*)d_in[0];
    const int*   pos     = (const int*)  d_in[2];
    const float* cosT    = (const float*)d_in[3];
    const float* sinT    = (const float*)d_in[4];
    const float* q_a_w   = (const float*)d_in[5];
    const float* q_a_ln  = (const float*)d_in[6];
    const float* q_b_w   = (const float*)d_in[7];
    const float* kv_a_w  = (const float*)d_in[8];
    const float* kv_a_ln = (const float*)d_in[9];
    const float* kv_b_w  = (const float*)d_in[10];
    const float* o_w     = (const float*)d_in[11];
    float* out = (float*)d_out;
    float* out_cache = out + (size_t)S_ * HID_;

    __half *xc, *wqa, *wqb, *wkva, *wkvb, *wo, *qn, *cnorm, *Q, *K, *V, *attn;
    float *qa, *ckv, *kpe, *q, *kv;
    cudaGetSymbolAddress((void**)&xc,     g_x);
    cudaGetSymbolAddress((void**)&wqa,    g_wqa);
    cudaGetSymbolAddress((void**)&wqb,    g_wqb);
    cudaGetSymbolAddress((void**)&wkva,   g_wkva);
    cudaGetSymbolAddress((void**)&wkvb,   g_wkvb);
    cudaGetSymbolAddress((void**)&wo,     g_wo);
    cudaGetSymbolAddress((void**)&qa,     g_qa);
    cudaGetSymbolAddress((void**)&qn,     g_qn);
    cudaGetSymbolAddress((void**)&ckv,    g_ckv);
    cudaGetSymbolAddress((void**)&cnorm,  g_cnorm);
    cudaGetSymbolAddress((void**)&kpe,    g_kpe);
    cudaGetSymbolAddress((void**)&q,      g_q);
    cudaGetSymbolAddress((void**)&kv,     g_kv);
    cudaGetSymbolAddress((void**)&Q,      g_Q);
    cudaGetSymbolAddress((void**)&K,      g_K);
    cudaGetSymbolAddress((void**)&V,      g_V);
    cudaGetSymbolAddress((void**)&attn,   g_attn);

    cudaFuncSetAttribute(pgemm_kernel, cudaFuncAttributeMaxDynamicSharedMemorySize, SMEM_P);
    cudaFuncSetAttribute(flash_kernel, cudaFuncAttributeMaxDynamicSharedMemorySize, FLASH_SMEM);

    auto conv = [&](const float* s, __half* d, int n) {
        conv_h_kernel<<<(n / 4 + 255) / 256, 256>>>(
            reinterpret_cast<const float4*>(s), reinterpret_cast<__half2*>(d), n / 4);
    };
    conv(x, xc, S_ * HID_);
    conv(q_a_w, wqa, HID_ * QL_);
    conv(q_b_w, wqb, QL_ * QDIM);
    conv(kv_b_w, wkvb, KVL_ * KVDIM);
    conv(o_w, wo, H_ * D_V * HID_);
    pad_kva_kernel<<<(HID_ * KVA_PAD + 255) / 256, 256>>>(kv_a_w, wkva);

    dim3 blk5(512);

    // 1+2) fused: qa = x@q_a_w ; ckv = x@kv_a_w (padded)
    pgemm_kernel<<<dim3(9, S_/128), blk5, SMEM_P>>>(
        xc, HID_, wqa, QL_, qa, QL_, QL_, 6,
        wkva, KVA_PAD, ckv, CKV_W, CKV_W, HID_);
    // 3) RMSNorm q_a -> fp16
    rms_q_kernel<<<S_, 256>>>(qa, q_a_ln, qn);
    // 4) RMSNorm ckv -> cnorm(fp16) + RoPE k_pe + kv_cache
    rms_ckv_kernel<<<S_, 256>>>(ckv, kv_a_ln, cosT, sinT, pos, cnorm, kpe, out_cache);
    // 5) q = qn @ q_b_w
    pgemm_kernel<<<dim3(QDIM/256, S_/128), blk5, SMEM_P>>>(
        qn, QL_, wqb, QDIM, q, QDIM, QDIM, QDIM/256,
        nullptr, 0, nullptr, 0, 0, QL_);
    // 6) kv = cnorm @ kv_b_w
    pgemm_kernel<<<dim3(KVDIM/256, S_/128), blk5, SMEM_P>>>(
        cnorm, KVL_, wkvb, KVDIM, kv, KVDIM, KVDIM, KVDIM/256,
        nullptr, 0, nullptr, 0, 0, KVL_);
    // 7) assemble Q/K + V transpose
    assemble_kernel<<<dim3(S_, H_), dim3(QHEAD)>>>(q, kv, kpe, cosT, sinT, pos, Q, K);
    vtrans_kernel<<<dim3(S_/64, H_), 256>>>(kv, V);
    // 8) fused flash attention
    flash_kernel<<<dim3(S_/64, H_), 256, FLASH_SMEM>>>(Q, K, V, attn);
    // 9) out = attn @ o_w
    pgemm_kernel<<<dim3(HID_/256, S_/128), blk5, SMEM_P>>>(
        attn, H_*D_V, wo, HID_, out, HID_, HID_, HID_/256,
        nullptr, 0, nullptr, 0, 0, H_*D_V);
}

// round 7
// speedup vs baseline: 5.3457x; 1.0694x over previous
#include <cuda_runtime.h>
#include <cuda_fp16.h>
#include <mma.h>
#include <math.h>
#include <stdint.h>

using namespace nvcuda;

// ---------------- problem constants ----------------
#define S_      2048
#define HID_    2048
#define H_      16
#define D_NOPE  128
#define D_ROPE  64
#define D_V     128
#define QHEAD   192
#define QL_     1536
#define KVL_    512
#define CKV_W   576
#define KVA_PAD 768
#define QDIM    3072
#define KVDIM   4096
#define EPS_    1e-6f
#define SCALE_  0.07216878364870322f

// ---------------- scratch ----------------
__device__ __half g_x     [S_ * HID_];
__device__ __half g_wqa   [HID_ * QL_];
__device__ __half g_wqb   [QL_ * QDIM];
__device__ __half g_wkva  [HID_ * KVA_PAD];   // zero-padded 576->768
__device__ __half g_wkvb  [KVL_ * KVDIM];
__device__ __half g_wo    [H_ * D_V * HID_];
__device__ float  g_qa    [S_ * QL_];
__device__ __half g_qn    [S_ * QL_];
__device__ float  g_ckv   [S_ * CKV_W];
__device__ __half g_cnorm [S_ * KVL_];
__device__ float  g_kpe   [S_ * D_ROPE];
__device__ float  g_q     [S_ * QDIM];
__device__ float  g_kv    [S_ * KVDIM];
__device__ __half g_Q     [H_ * S_ * QHEAD];  // k-dim perm16
__device__ __half g_K     [H_ * S_ * QHEAD];  // k-dim perm16
__device__ __half g_V     [H_ * D_V * S_];    // per-head transposed, s perm16
__device__ __half g_attn  [S_ * (H_ * D_V)];

__device__ __forceinline__ int perm16(int c) {
    int j = c & 15;
    return (c & ~15) | (((j >> 1) & 3) << 2) | ((j >> 3) << 1) | (j & 1);
}
__device__ __forceinline__ uint32_t smem_u32(const void* p) {
    uint32_t a;
    asm("{ .reg .u64 t; cvta.to.shared.u64 t, %1; cvt.u32.u64 %0, t; }" : "=r"(a) : "l"(p));
    return a;
}
__device__ __forceinline__ void cp16(uint32_t d, const void* s) {
    asm volatile("cp.async.ca.shared.global [%0], [%1], 16;" :: "r"(d), "l"(s));
}
__device__ __forceinline__ void cp_commit() {
    asm volatile("cp.async.commit_group;" ::: "memory");
}
template<int N> __device__ __forceinline__ void cp_wait() {
    asm volatile("cp.async.wait_group %0;" :: "n"(N) : "memory");
}
__device__ __forceinline__ void mma16(float* c, uint32_t a0, uint32_t a1, uint32_t a2, uint32_t a3,
                                      uint32_t b0, uint32_t b1) {
    asm volatile(
        "mma.sync.aligned.m16n8k16.row.col.f32.f16.f16.f32 "
        "{%0,%1,%2,%3}, {%4,%5,%6,%7}, {%8,%9}, {%0,%1,%2,%3};"
        : "+f"(c[0]), "+f"(c[1]), "+f"(c[2]), "+f"(c[3])
        : "r"(a0), "r"(a1), "r"(a2), "r"(a3), "r"(b0), "r"(b1));
}

// ---------------- prep: fused fp16 conversion (5 tensors, 1 launch) ----------------
__global__ void conv_multi_kernel(
    const float4* __restrict__ s0, __half2* __restrict__ d0, int n0,
    const float4* __restrict__ s1, __half2* __restrict__ d1, int n1,
    const float4* __restrict__ s2, __half2* __restrict__ d2, int n2,
    const float4* __restrict__ s3, __half2* __restrict__ d3, int n3,
    const float4* __restrict__ s4, __half2* __restrict__ d4, int n4)
{
    int i = blockIdx.x * blockDim.x + threadIdx.x;
    const float4* s; __half2* d; int j = i;
    if      (j < n0)                  { s = s0; d = d0; }
    else if ((j -= n0) < n1)          { s = s1; d = d1; }
    else if ((j -= n1) < n2)          { s = s2; d = d2; }
    else if ((j -= n2) < n3)          { s = s3; d = d3; }
    else if ((j -= n3) < n4)          { s = s4; d = d4; }
    else return;
    float4 v = s[j];
    d[2 * j + 0] = __floats2half2_rn(v.x, v.y);
    d[2 * j + 1] = __floats2half2_rn(v.z, v.w);
}
__global__ void pad_kva_kernel(const float* __restrict__ src, __half* __restrict__ dst)
{
    int i = blockIdx.x * blockDim.x + threadIdx.x;
    if (i < HID_ * KVA_PAD) {
        int k = i / KVA_PAD, n = i % KVA_PAD;
        dst[i] = (n < CKV_W) ? __float2half(src[k * CKV_W + n]) : __half(0.f);
    }
}

// ---------------- pipelined fp16 GEMM ----------------
// BM=128, BN=256, BK=64, 512 threads, 3-stage cp.async
#define A_STRH 72     // halfs: 64 + 8 pad (144B row)
#define B_STRH 264    // halfs: 256 + 8 pad (528B row)
#define A_SBYT (128 * A_STRH * 2)   // 18432
#define B_SBYT (64 * B_STRH * 2)    // 33792
#define STG_P  (A_SBYT + B_SBYT)    // 52224
#define SMEM_P (3 * STG_P)          // 156672

__global__ __launch_bounds__(512, 1)
void pgemm_kernel(const __half* __restrict__ A, int lda,
                  const __half* __restrict__ B, int ldb,
                  float* __restrict__ C, int ldc, int N, int nt1,
                  const __half* __restrict__ B2, int ldb2,
                  float* __restrict__ C2, int ldc2, int N2,
                  int K)
{
    int bx = blockIdx.x;
    if (bx >= nt1) { B = B2; ldb = ldb2; C = C2; ldc = ldc2; N = N2; bx -= nt1; }
    const int row0 = blockIdx.y * 128;
    const int col0 = bx * 256;
    const int nk = K / 64;

    extern __shared__ char smem[];
    const uint32_t sb = smem_u32(smem);
    const int tid = threadIdx.x;
    const int wid = tid >> 5;
    const int wm  = wid >> 3;
    const int wn  = wid & 7;

    auto issue = [&](int t) {
        const int s = t % 3;
        const int k0 = t * 64;
        uint32_t ab = sb + s * STG_P;
        #pragma unroll
        for (int i = 0; i < 2; i++) {
            int idx = i * 512 + tid;
            int r = idx >> 3, c = idx & 7;
            cp16(ab + r * (A_STRH * 2) + c * 16, A + (size_t)(row0 + r) * lda + k0 + c * 8);
        }
        uint32_t bb = sb + s * STG_P + A_SBYT;
        #pragma unroll
        for (int i = 0; i < 4; i++) {
            int idx = i * 512 + tid;
            int kr = idx >> 5, c = idx & 31;
            cp16(bb + kr * (B_STRH * 2) + c * 16, B + (size_t)(k0 + kr) * ldb + col0 + c * 8);
        }
    };

    typedef wmma::fragment<wmma::matrix_a, 16, 16, 16, __half, wmma::row_major> AFrag;
    typedef wmma::fragment<wmma::matrix_b, 16, 16, 16, __half, wmma::row_major> BFrag;
    wmma::fragment<wmma::accumulator, 16, 16, 16, float> acc[4][2];
    #pragma unroll
    for (int i = 0; i < 4; i++)
        #pragma unroll
        for (int j = 0; j < 2; j++) wmma::fill_fragment(acc[i][j], 0.0f);

    issue(0); cp_commit();
    if (nk > 1) { issue(1); cp_commit(); }

    for (int t = 0; t < nk; t++) {
        if (t + 1 < nk) cp_wait<1>(); else cp_wait<0>();
        __syncthreads();
        if (t + 2 < nk) { issue(t + 2); cp_commit(); }

        const __half* As = reinterpret_cast<const __half*>(smem + (t % 3) * STG_P);
        const __half* Bs = reinterpret_cast<const __half*>(smem + (t % 3) * STG_P + A_SBYT);

        #pragma unroll
        for (int kk = 0; kk < 4; kk++) {
            AFrag af[4];
            BFrag bf[2];
            #pragma unroll
            for (int mf = 0; mf < 4; mf++)
                wmma::load_matrix_sync(af[mf], As + (wm * 64 + mf * 16) * A_STRH + kk * 16, A_STRH);
            #pragma unroll
            for (int nf = 0; nf < 2; nf++)
                wmma::load_matrix_sync(bf[nf], Bs + (kk * 16) * B_STRH + wn * 32 + nf * 16, B_STRH);
            #pragma unroll
            for (int mf = 0; mf < 4; mf++)
                #pragma unroll
                for (int nf = 0; nf < 2; nf++)
                    wmma::mma_sync(acc[mf][nf], af[mf], bf[nf], acc[mf][nf]);
        }
        __syncthreads();
    }

    #pragma unroll
    for (int mf = 0; mf < 4; mf++) {
        int gr = row0 + wm * 64 + mf * 16;
        #pragma unroll
        for (int nf = 0; nf < 2; nf++) {
            int gc = col0 + wn * 32 + nf * 16;
            if (gc + 16 <= N)
                wmma::store_matrix_sync(C + (size_t)gr * ldc + gc, acc[mf][nf], ldc,
                                        wmma::mem_row_major);
        }
    }
}

// ---------------- RMSNorm q_a (emits fp16) ----------------
__global__ __launch_bounds__(256)
void rms_q_kernel(const float* __restrict__ in, const float* __restrict__ w,
                  __half* __restrict__ out)
{
    const int s = blockIdx.x;
    const float* x = in + (size_t)s * QL_;
    __half*      y = out + (size_t)s * QL_;
    const int tid = threadIdx.x;

    float v[6];
    float local = 0.f;
    #pragma unroll
    for (int i = 0; i < 6; i++) { int c = tid + i * 256; v[i] = x[c]; local += v[i] * v[i]; }
    __shared__ float sred[256];
    sred[tid] = local; __syncthreads();
    for (int st = 128; st > 0; st >>= 1) {
        if (tid < st) sred[tid] += sred[tid + st];
        __syncthreads();
    }
    float scale = rsqrtf(sred[0] / (float)QL_ + EPS_);
    #pragma unroll
    for (int i = 0; i < 6; i++) { int c = tid + i * 256; y[c] = __float2half(v[i] * scale * w[c]); }
}

// ---------------- RMSNorm ckv (cnorm fp16, cache fp32) + RoPE k_pe ----------------
__global__ __launch_bounds__(256)
void rms_ckv_kernel(const float* __restrict__ ckv, const float* __restrict__ w,
                    const float* __restrict__ cosT, const float* __restrict__ sinT,
                    const int* __restrict__ pos,
                    __half* __restrict__ cnorm, float* __restrict__ kpe,
                    float* __restrict__ cache)
{
    const int s = blockIdx.x;
    const float* x = ckv + (size_t)s * CKV_W;
    const int tid = threadIdx.x;

    float v[2];
    float local = 0.f;
    #pragma unroll
    for (int i = 0; i < 2; i++) { int c = tid + i * 256; v[i] = x[c]; local += v[i] * v[i]; }
    __shared__ float sred[256];
    sred[tid] = local; __syncthreads();
    for (int st = 128; st > 0; st >>= 1) {
        if (tid < st) sred[tid] += sred[tid + st];
        __syncthreads();
    }
    float scale = rsqrtf(sred[0] / (float)KVL_ + EPS_);
    #pragma unroll
    for (int i = 0; i < 2; i++) {
        int c = tid + i * 256;
        float y = v[i] * scale * w[c];
        cnorm[(size_t)s * KVL_ + c] = __float2half(y);
        cache[(size_t)s * CKV_W + c] = y;
    }
    if (tid < D_ROPE) {
        int p = pos[s];
        const float* cr = cosT + (size_t)p * D_ROPE;
        const float* sr = sinT + (size_t)p * D_ROPE;
        const float* t  = x + KVL_;
        int i = tid;
        float val;
        if (i < 32) val = t[2 * i] * cr[i] - t[2 * i + 1] * sr[i];
        else { int i2 = i - 32; val = t[2 * i2 + 1] * cr[i] + t[2 * i2] * sr[i]; }
        kpe[(size_t)s * D_ROPE + i] = val;
        cache[(size_t)s * CKV_W + KVL_ + i] = val;
    }
}

// ---------------- assemble Q/K (fp16, k-dim perm16) ----------------
__global__ void assemble_kernel(const float* __restrict__ q, const float* __restrict__ kv,
                                const float* __restrict__ kpe,
                                const float* __restrict__ cosT, const float* __restrict__ sinT,
                                const int* __restrict__ pos,
                                __half* __restrict__ Q, __half* __restrict__ K)
{
    const int s = blockIdx.x;
    const int h = blockIdx.y;
    const int d = threadIdx.x;
    const float* qrow  = q  + (size_t)s * QDIM  + h * QHEAD;
    const float* kvrow = kv + (size_t)s * KVDIM + h * (D_NOPE + D_V);
    const size_t off = ((size_t)h * S_ + s) * QHEAD;

    float qv;
    if (d < D_NOPE) qv = qrow[d];
    else {
        int p = pos[s];
        const float* cr = cosT + (size_t)p * D_ROPE;
        const float* sr = sinT + (size_t)p * D_ROPE;
        const float* t  = qrow + D_NOPE;
        int i = d - D_NOPE;
        if (i < 32) qv = t[2 * i] * cr[i] - t[2 * i + 1] * sr[i];
        else { int i2 = i - 32; qv = t[2 * i2 + 1] * cr[i] + t[2 * i2] * sr[i]; }
    }
    float kvv = (d < D_NOPE) ? kvrow[d] : kpe[(size_t)s * D_ROPE + (d - D_NOPE)];
    int pd = perm16(d);
    Q[off + pd] = __float2half(qv);
    K[off + pd] = __float2half(kvv);
}

// ---------------- V transpose: g_V[h][d][s] fp16, s perm16 ----------------
__global__ __launch_bounds__(256)
void vtrans_kernel(const float* __restrict__ kv, __half* __restrict__ V)
{
    const int s0 = blockIdx.x * 64;
    const int h  = blockIdx.y;
    const int tid = threadIdx.x;
    __shared__ float vt[64 * 133];

    #pragma unroll
    for (int i = 0; i < 32; i++) {
        int idx = i * 256 + tid;
        int sl = idx >> 7, d = idx & 127;
        vt[sl * 133 + d] = kv[(size_t)(s0 + sl) * KVDIM + h * (D_NOPE + D_V) + D_NOPE + d];
    }
    __syncthreads();
    #pragma unroll
    for (int i = 0; i < 32; i++) {
        int idx = i * 256 + tid;
        int d = idx >> 6, sl = idx & 63;
        V[((size_t)h * D_V + d) * S_ + s0 + perm16(sl)] = __float2half(vt[sl * 133 + d]);
    }
}

// ---------------- fused flash attention (fp16) ----------------
#define QS_STR 200   // halfs (400B)
#define KS_STR 200
#define VS_STR 40    // halfs (80B)
#define SF_STR 36    // floats
#define PH_STR 40    // halfs
#define QS_OFF 0
#define KS_OFF 25600
#define KS_BYTES 12800
#define VS_OFF (KS_OFF + 2*KS_BYTES)     // 51200
#define VS_BYTES 10240
#define SF_OFF (VS_OFF + 2*VS_BYTES)     // 71680
#define PH_OFF (SF_OFF + 64*SF_STR*4)    // 80896
#define M_OFF  (PH_OFF + 64*PH_STR*2)    // 86016
#define L_OFF  (M_OFF + 256)
#define AL_OFF (L_OFF + 256)
#define FLASH_SMEM (AL_OFF + 256)

__global__ __launch_bounds__(256, 2)
void flash_kernel(const __half* __restrict__ Q, const __half* __restrict__ K,
                  const __half* __restrict__ V, __half* __restrict__ attn)
{
    const int qt = blockIdx.x;
    const int h  = blockIdx.y;
    const int q0 = qt * 64;
    const int nt = 2 * qt + 2;

    extern __shared__ char sm[];
    const uint32_t sb = smem_u32(sm);
    float* mP = reinterpret_cast<float*>(sm + M_OFF);
    float* lP = reinterpret_cast<float*>(sm + L_OFF);
    float* aP = reinterpret_cast<float*>(sm + AL_OFF);

    const int tid = threadIdx.x;
    const int wid = tid >> 5;
    const int lid = tid & 31;
    const int gl  = lid >> 2;
    const int tg  = lid & 3;
    const int wm  = wid >> 2;
    const int wn  = wid & 3;

    const __half* Qg = Q + ((size_t)h * S_ + q0) * QHEAD;
    const __half* Kg = K + (size_t)h * S_ * QHEAD;
    const __half* Vg = V + (size_t)h * D_V * S_;

    auto issueKV = [&](int t, int st) {
        const __half* kp = Kg + (size_t)t * 32 * QHEAD;
        uint32_t kd = sb + KS_OFF + st * KS_BYTES;
        #pragma unroll
        for (int i = 0; i < 3; i++) {
            int idx = i * 256 + tid;
            int r = idx / 24, c = idx % 24;
            cp16(kd + r * (KS_STR * 2) + c * 16, kp + (size_t)r * QHEAD + c * 8);
        }
        uint32_t vd = sb + VS_OFF + st * VS_BYTES;
        #pragma unroll
        for (int i = 0; i < 2; i++) {
            int idx = i * 256 + tid;
            int d = idx >> 2, c = idx & 3;
            cp16(vd + d * (VS_STR * 2) + c * 16, Vg + (size_t)d * S_ + t * 32 + c * 8);
        }
    };

    #pragma unroll
    for (int i = 0; i < 6; i++) {
        int idx = i * 256 + tid;
        int r = idx / 24, c = idx % 24;
        cp16(sb + QS_OFF + r * (QS_STR * 2) + c * 16, Qg + (size_t)r * QHEAD + c * 8);
    }
    issueKV(0, 0);
    cp_commit();

    if (tid < 64) { mP[tid] = -1e30f; lP[tid] = 0.f; }

    float oacc[2][4][4];
    #pragma unroll
    for (int a = 0; a < 2; a++)
        #pragma unroll
        for (int b = 0; b < 4; b++)
            #pragma unroll
            for (int c = 0; c < 4; c++) oacc[a][b][c] = 0.f;

    const char* QsB = sm + QS_OFF;
    char* SfB = sm + SF_OFF;
    char* PhB = sm + PH_OFF;

    for (int t = 0; t < nt; t++) {
        const int st = t & 1;
        if (t + 1 < nt) { issueKV(t + 1, st ^ 1); cp_commit(); cp_wait<1>(); }
        else            { cp_wait<0>(); }
        __syncthreads();

        // ---- S = Q K^T ----
        const char* KsB = sm + KS_OFF + st * KS_BYTES;
        float sacc[2][4] = {{0.f,0.f,0.f,0.f},{0.f,0.f,0.f,0.f}};
        const int bRow = wn * 8 + gl;
        #pragma unroll 4
        for (int kk = 0; kk < 12; kk++) {
            uint2 bb = *reinterpret_cast<const uint2*>(
                KsB + (bRow * KS_STR + kk * 16 + 4 * tg) * 2);
            #pragma unroll
            for (int mf = 0; mf < 2; mf++) {
                int r0 = wm * 32 + mf * 16 + gl;
                uint2 lo = *reinterpret_cast<const uint2*>(
                    QsB + (r0 * QS_STR + kk * 16 + 4 * tg) * 2);
                uint2 hi = *reinterpret_cast<const uint2*>(
                    QsB + ((r0 + 8) * QS_STR + kk * 16 + 4 * tg) * 2);
                mma16(sacc[mf], lo.x, hi.x, lo.y, hi.y, bb.x, bb.y);
            }
        }
        #pragma unroll
        for (int mf = 0; mf < 2; mf++) {
            int r0 = wm * 32 + mf * 16 + gl;
            int c0 = wn * 8 + 2 * tg;
            *reinterpret_cast<float2*>(SfB + (r0 * SF_STR + c0) * 4) =
                make_float2(sacc[mf][0], sacc[mf][1]);
            *reinterpret_cast<float2*>(SfB + ((r0 + 8) * SF_STR + c0) * 4) =
                make_float2(sacc[mf][2], sacc[mf][3]);
        }
        __syncthreads();

        // ---- online softmax ----
        {
            const int row = tid >> 2;
            const int cb  = (tid & 3) * 8;
            float* srow = reinterpret_cast<float*>(SfB) + row * SF_STR + cb;
            __half* prow = reinterpret_cast<__half*>(PhB) + row * PH_STR;
            float4 v0 = *reinterpret_cast<float4*>(srow);
            float4 v1 = *reinterpret_cast<float4*>(srow + 4);
            float v[8] = {v0.x, v0.y, v0.z, v0.w, v1.x, v1.y, v1.z, v1.w};
            const int rg = q0 + row;
            const int key0 = t * 32 + cb;
            const bool msk = (t >= 2 * qt);
            float mx = -1e30f;
            #pragma unroll
            for (int j = 0; j < 8; j++) {
                float val = v[j] * SCALE_;
                if (msk && (key0 + j) > rg) val = -1e30f;
                v[j] = val;
                mx = fmaxf(mx, val);
            }
            mx = fmaxf(mx, __shfl_xor_sync(0xffffffffu, mx, 1));
            mx = fmaxf(mx, __shfl_xor_sync(0xffffffffu, mx, 2));
            float mold = mP[row];
            float mnew = fmaxf(mold, mx);
            float al = __expf(mold - mnew);
            float sum = 0.f;
            #pragma unroll
            for (int j = 0; j < 8; j++) {
                float p = __expf(v[j] - mnew);
                sum += p;
                prow[perm16(cb + j)] = __float2half(p);
            }
            sum += __shfl_xor_sync(0xffffffffu, sum, 1);
            sum += __shfl_xor_sync(0xffffffffu, sum, 2);
            if ((tid & 3) == 0) {
                mP[row] = mnew;
                lP[row] = lP[row] * al + sum;
                aP[row] = al;
            }
        }
        __syncthreads();

        // ---- rescale O, then O += P V ----
        const char* VsB = sm + VS_OFF + st * VS_BYTES;
        #pragma unroll
        for (int mf = 0; mf < 2; mf++) {
            int r0 = wm * 32 + mf * 16 + gl;
            float a0 = aP[r0], a8 = aP[r0 + 8];
            #pragma unroll
            for (int nf = 0; nf < 4; nf++) {
                oacc[mf][nf][0] *= a0; oacc[mf][nf][1] *= a0;
                oacc[mf][nf][2] *= a8; oacc[mf][nf][3] *= a8;
            }
        }
        #pragma unroll
        for (int kk = 0; kk < 2; kk++) {
            uint2 alo[2], ahi[2];
            #pragma unroll
            for (int mf = 0; mf < 2; mf++) {
                int r0 = wm * 32 + mf * 16 + gl;
                alo[mf] = *reinterpret_cast<const uint2*>(
                    PhB + (r0 * PH_STR + kk * 16 + 4 * tg) * 2);
                ahi[mf] = *reinterpret_cast<const uint2*>(
                    PhB + ((r0 + 8) * PH_STR + kk * 16 + 4 * tg) * 2);
            }
            #pragma unroll
            for (int nf = 0; nf < 4; nf++) {
                int nc = wn * 32 + nf * 8 + gl;
                uint2 bv = *reinterpret_cast<const uint2*>(
                    VsB + (nc * VS_STR + kk * 16 + 4 * tg) * 2);
                #pragma unroll
                for (int mf = 0; mf < 2; mf++)
                    mma16(oacc[mf][nf], alo[mf].x, ahi[mf].x, alo[mf].y, ahi[mf].y, bv.x, bv.y);
            }
        }
        __syncthreads();
    }

    // ---- epilogue ----
    #pragma unroll
    for (int mf = 0; mf < 2; mf++) {
        int r0 = wm * 32 + mf * 16 + gl;
        float inv0 = 1.f / lP[r0];
        float inv8 = 1.f / lP[r0 + 8];
        #pragma unroll
        for (int nf = 0; nf < 4; nf++) {
            int col = h * D_V + wn * 32 + nf * 8 + 2 * tg;
            __half2* o0 = reinterpret_cast<__half2*>(attn + (size_t)(q0 + r0) * (H_ * D_V) + col);
            __half2* o8 = reinterpret_cast<__half2*>(attn + (size_t)(q0 + r0 + 8) * (H_ * D_V) + col);
            *o0 = __floats2half2_rn(oacc[mf][nf][0] * inv0, oacc[mf][nf][1] * inv0);
            *o8 = __floats2half2_rn(oacc[mf][nf][2] * inv8, oacc[mf][nf][3] * inv8);
        }
    }
}

// ---------------- host launch ----------------
extern "C" void kernel_launch(void* const* d_in, const int* in_sizes, int n_in,
                              void* d_out, int out_size)
{
    const float* x       = (const float*)d_in[0];
    const int*   pos     = (const int*)  d_in[2];
    const float* cosT    = (const float*)d_in[3];
    const float* sinT    = (const float*)d_in[4];
    const float* q_a_w   = (const float*)d_in[5];
    const float* q_a_ln  = (const float*)d_in[6];
    const float* q_b_w   = (const float*)d_in[7];
    const float* kv_a_w  = (const float*)d_in[8];
    const float* kv_a_ln = (const float*)d_in[9];
    const float* kv_b_w  = (const float*)d_in[10];
    const float* o_w     = (const float*)d_in[11];
    float* out = (float*)d_out;
    float* out_cache = out + (size_t)S_ * HID_;

    __half *xc, *wqa, *wqb, *wkva, *wkvb, *wo, *qn, *cnorm, *Q, *K, *V, *attn;
    float *qa, *ckv, *kpe, *q, *kv;
    cudaGetSymbolAddress((void**)&xc,     g_x);
    cudaGetSymbolAddress((void**)&wqa,    g_wqa);
    cudaGetSymbolAddress((void**)&wqb,    g_wqb);
    cudaGetSymbolAddress((void**)&wkva,   g_wkva);
    cudaGetSymbolAddress((void**)&wkvb,   g_wkvb);
    cudaGetSymbolAddress((void**)&wo,     g_wo);
    cudaGetSymbolAddress((void**)&qa,     g_qa);
    cudaGetSymbolAddress((void**)&qn,     g_qn);
    cudaGetSymbolAddress((void**)&ckv,    g_ckv);
    cudaGetSymbolAddress((void**)&cnorm,  g_cnorm);
    cudaGetSymbolAddress((void**)&kpe,    g_kpe);
    cudaGetSymbolAddress((void**)&q,      g_q);
    cudaGetSymbolAddress((void**)&kv,     g_kv);
    cudaGetSymbolAddress((void**)&Q,      g_Q);
    cudaGetSymbolAddress((void**)&K,      g_K);
    cudaGetSymbolAddress((void**)&V,      g_V);
    cudaGetSymbolAddress((void**)&attn,   g_attn);

    cudaFuncSetAttribute(pgemm_kernel, cudaFuncAttributeMaxDynamicSharedMemorySize, SMEM_P);
    cudaFuncSetAttribute(flash_kernel, cudaFuncAttributeMaxDynamicSharedMemorySize, FLASH_SMEM);

    // fused conversion: x + 4 weights (1 launch) + padded kv_a (1 launch)
    {
        int n0 = S_ * HID_ / 4, n1 = HID_ * QL_ / 4, n2 = QL_ * QDIM / 4,
            n3 = KVL_ * KVDIM / 4, n4 = H_ * D_V * HID_ / 4;
        int total = n0 + n1 + n2 + n3 + n4;
        conv_multi_kernel<<<(total + 255) / 256, 256>>>(
            (const float4*)x,      (__half2*)xc,   n0,
            (const float4*)q_a_w,  (__half2*)wqa,  n1,
            (const float4*)q_b_w,  (__half2*)wqb,  n2,
            (const float4*)kv_b_w, (__half2*)wkvb, n3,
            (const float4*)o_w,    (__half2*)wo,   n4);
        pad_kva_kernel<<<(HID_ * KVA_PAD + 255) / 256, 256>>>(kv_a_w, wkva);
    }

    dim3 blk5(512);

    // 1+2) fused: qa = x@q_a_w ; ckv = x@kv_a_w (padded)
    pgemm_kernel<<<dim3(9, S_/128), blk5, SMEM_P>>>(
        xc, HID_, wqa, QL_, qa, QL_, QL_, 6,
        wkva, KVA_PAD, ckv, CKV_W, CKV_W, HID_);
    // 3) RMSNorm q_a -> fp16
    rms_q_kernel<<<S_, 256>>>(qa, q_a_ln, qn);
    // 4) RMSNorm ckv -> cnorm(fp16) + RoPE k_pe + kv_cache
    rms_ckv_kernel<<<S_, 256>>>(ckv, kv_a_ln, cosT, sinT, pos, cnorm, kpe, out_cache);
    // 5) q = qn @ q_b_w
    pgemm_kernel<<<dim3(QDIM/256, S_/128), blk5, SMEM_P>>>(
        qn, QL_, wqb, QDIM, q, QDIM, QDIM, QDIM/256,
        nullptr, 0, nullptr, 0, 0, QL_);
    // 6) kv = cnorm @ kv_b_w
    pgemm_kernel<<<dim3(KVDIM/256, S_/128), blk5, SMEM_P>>>(
        cnorm, KVL_, wkvb, KVDIM, kv, KVDIM, KVDIM, KVDIM/256,
        nullptr, 0, nullptr, 0, 0, KVL_);
    // 7) assemble Q/K + V transpose
    assemble_kernel<<<dim3(S_, H_), dim3(QHEAD)>>>(q, kv, kpe, cosT, sinT, pos, Q, K);
    vtrans_kernel<<<dim3(S_/64, H_), 256>>>(kv, V);
    // 8) fused flash attention
    flash_kernel<<<dim3(S_/64, H_), 256, FLASH_SMEM>>>(Q, K, V, attn);
    // 9) out = attn @ o_w
    pgemm_kernel<<<dim3(HID_/256, S_/128), blk5, SMEM_P>>>(
        attn, H_*D_V, wo, HID_, out, HID_, HID_, HID_/256,
        nullptr, 0, nullptr, 0, 0, H_*D_V);
}

// round 8
// speedup vs baseline: 5.4864x; 1.0263x over previous
#include <cuda_runtime.h>
#include <cuda_fp16.h>
#include <mma.h>
#include <math.h>
#include <stdint.h>

using namespace nvcuda;

// ---------------- problem constants ----------------
#define S_      2048
#define HID_    2048
#define H_      16
#define D_NOPE  128
#define D_ROPE  64
#define D_V     128
#define QHEAD   192
#define QL_     1536
#define KVL_    512
#define CKV_W   576
#define KVA_PAD 768
#define QDIM    3072
#define KVDIM   4096
#define EPS_    1e-6f
#define SCALE_  0.07216878364870322f

// ---------------- scratch ----------------
__device__ __half g_x     [S_ * HID_];
__device__ __half g_wqa   [HID_ * QL_];
__device__ __half g_wqb   [QL_ * QDIM];
__device__ __half g_wkva  [HID_ * KVA_PAD];
__device__ __half g_wkvb  [KVL_ * KVDIM];
__device__ __half g_wo    [H_ * D_V * HID_];
__device__ float  g_qa    [S_ * QL_];
__device__ __half g_qn    [S_ * QL_];
__device__ float  g_ckv   [S_ * CKV_W];
__device__ __half g_cnorm [S_ * KVL_];
__device__ float  g_kpe   [S_ * D_ROPE];
__device__ float  g_q     [S_ * QDIM];
__device__ float  g_kv    [S_ * KVDIM];
__device__ __half g_Q     [H_ * S_ * QHEAD];
__device__ __half g_K     [H_ * S_ * QHEAD];
__device__ __half g_V     [H_ * D_V * S_];
__device__ __half g_attn  [S_ * (H_ * D_V)];

__device__ __forceinline__ int perm16(int c) {
    int j = c & 15;
    return (c & ~15) | (((j >> 1) & 3) << 2) | ((j >> 3) << 1) | (j & 1);
}
__device__ __forceinline__ uint32_t smem_u32(const void* p) {
    uint32_t a;
    asm("{ .reg .u64 t; cvta.to.shared.u64 t, %1; cvt.u32.u64 %0, t; }" : "=r"(a) : "l"(p));
    return a;
}
__device__ __forceinline__ void cp16(uint32_t d, const void* s) {
    asm volatile("cp.async.ca.shared.global [%0], [%1], 16;" :: "r"(d), "l"(s));
}
__device__ __forceinline__ void cp_commit() {
    asm volatile("cp.async.commit_group;" ::: "memory");
}
template<int N> __device__ __forceinline__ void cp_wait() {
    asm volatile("cp.async.wait_group %0;" :: "n"(N) : "memory");
}
__device__ __forceinline__ void mma16(float* c, uint32_t a0, uint32_t a1, uint32_t a2, uint32_t a3,
                                      uint32_t b0, uint32_t b1) {
    asm volatile(
        "mma.sync.aligned.m16n8k16.row.col.f32.f16.f16.f32 "
        "{%0,%1,%2,%3}, {%4,%5,%6,%7}, {%8,%9}, {%0,%1,%2,%3};"
        : "+f"(c[0]), "+f"(c[1]), "+f"(c[2]), "+f"(c[3])
        : "r"(a0), "r"(a1), "r"(a2), "r"(a3), "r"(b0), "r"(b1));
}

// ---------------- prep: fused fp16 conversion (5 tensors + padded kv_a, 1 launch) ----------------
__global__ void conv_multi_kernel(
    const float4* __restrict__ s0, __half2* __restrict__ d0, int n0,
    const float4* __restrict__ s1, __half2* __restrict__ d1, int n1,
    const float4* __restrict__ s2, __half2* __restrict__ d2, int n2,
    const float4* __restrict__ s3, __half2* __restrict__ d3, int n3,
    const float4* __restrict__ s4, __half2* __restrict__ d4, int n4,
    const float* __restrict__ kva, __half* __restrict__ wkva, int n5)
{
    int i = blockIdx.x * blockDim.x + threadIdx.x;
    int j = i;
    if (j < n0) {
        float4 v = s0[j];
        d0[2*j+0] = __floats2half2_rn(v.x, v.y); d0[2*j+1] = __floats2half2_rn(v.z, v.w);
        return;
    }
    j -= n0;
    if (j < n1) {
        float4 v = s1[j];
        d1[2*j+0] = __floats2half2_rn(v.x, v.y); d1[2*j+1] = __floats2half2_rn(v.z, v.w);
        return;
    }
    j -= n1;
    if (j < n2) {
        float4 v = s2[j];
        d2[2*j+0] = __floats2half2_rn(v.x, v.y); d2[2*j+1] = __floats2half2_rn(v.z, v.w);
        return;
    }
    j -= n2;
    if (j < n3) {
        float4 v = s3[j];
        d3[2*j+0] = __floats2half2_rn(v.x, v.y); d3[2*j+1] = __floats2half2_rn(v.z, v.w);
        return;
    }
    j -= n3;
    if (j < n4) {
        float4 v = s4[j];
        d4[2*j+0] = __floats2half2_rn(v.x, v.y); d4[2*j+1] = __floats2half2_rn(v.z, v.w);
        return;
    }
    j -= n4;
    if (j < n5) {
        // padded kv_a: j indexes groups of 4 dst halfs; 576%4==0 so group never straddles
        int k = (4 * j) / KVA_PAD, n = (4 * j) % KVA_PAD;
        __half2 lo, hi;
        if (n < CKV_W) {
            float4 v = *reinterpret_cast<const float4*>(kva + (size_t)k * CKV_W + n);
            lo = __floats2half2_rn(v.x, v.y); hi = __floats2half2_rn(v.z, v.w);
        } else {
            lo = __floats2half2_rn(0.f, 0.f); hi = lo;
        }
        __half2* dp = reinterpret_cast<__half2*>(wkva + (size_t)k * KVA_PAD + n);
        dp[0] = lo; dp[1] = hi;
    }
}

// ---------------- pipelined fp16 GEMM, dual problem sets ----------------
// BM=128, BN=256, BK=64, 512 threads, 3-stage cp.async
#define A_STRH 72
#define B_STRH 264
#define A_SBYT (128 * A_STRH * 2)
#define B_SBYT (64 * B_STRH * 2)
#define STG_P  (A_SBYT + B_SBYT)
#define SMEM_P (3 * STG_P)

__global__ __launch_bounds__(512, 1)
void pgemm_kernel(const __half* __restrict__ A, int lda, int K,
                  const __half* __restrict__ B, int ldb,
                  float* __restrict__ C, int ldc, int N, int nt1,
                  const __half* __restrict__ A2, int lda2, int K2,
                  const __half* __restrict__ B2, int ldb2,
                  float* __restrict__ C2, int ldc2, int N2)
{
    int bx = blockIdx.x;
    if (bx >= nt1) {
        A = A2; lda = lda2; K = K2; B = B2; ldb = ldb2; C = C2; ldc = ldc2; N = N2;
        bx -= nt1;
    }
    const int row0 = blockIdx.y * 128;
    const int col0 = bx * 256;
    const int nk = K / 64;

    extern __shared__ char smem[];
    const uint32_t sb = smem_u32(smem);
    const int tid = threadIdx.x;
    const int wid = tid >> 5;
    const int wm  = wid >> 3;
    const int wn  = wid & 7;

    auto issue = [&](int t) {
        const int s = t % 3;
        const int k0 = t * 64;
        uint32_t ab = sb + s * STG_P;
        #pragma unroll
        for (int i = 0; i < 2; i++) {
            int idx = i * 512 + tid;
            int r = idx >> 3, c = idx & 7;
            cp16(ab + r * (A_STRH * 2) + c * 16, A + (size_t)(row0 + r) * lda + k0 + c * 8);
        }
        uint32_t bb = sb + s * STG_P + A_SBYT;
        #pragma unroll
        for (int i = 0; i < 4; i++) {
            int idx = i * 512 + tid;
            int kr = idx >> 5, c = idx & 31;
            cp16(bb + kr * (B_STRH * 2) + c * 16, B + (size_t)(k0 + kr) * ldb + col0 + c * 8);
        }
    };

    typedef wmma::fragment<wmma::matrix_a, 16, 16, 16, __half, wmma::row_major> AFrag;
    typedef wmma::fragment<wmma::matrix_b, 16, 16, 16, __half, wmma::row_major> BFrag;
    wmma::fragment<wmma::accumulator, 16, 16, 16, float> acc[4][2];
    #pragma unroll
    for (int i = 0; i < 4; i++)
        #pragma unroll
        for (int j = 0; j < 2; j++) wmma::fill_fragment(acc[i][j], 0.0f);

    issue(0); cp_commit();
    if (nk > 1) { issue(1); cp_commit(); }

    for (int t = 0; t < nk; t++) {
        if (t + 1 < nk) cp_wait<1>(); else cp_wait<0>();
        __syncthreads();
        // Safe to refill slot (t+2)%3 == (t-1)%3 here: every warp finished its
        // iter t-1 reads (program order) before reaching the barrier above.
        if (t + 2 < nk) { issue(t + 2); cp_commit(); }

        const __half* As = reinterpret_cast<const __half*>(smem + (t % 3) * STG_P);
        const __half* Bs = reinterpret_cast<const __half*>(smem + (t % 3) * STG_P + A_SBYT);

        #pragma unroll
        for (int kk = 0; kk < 4; kk++) {
            AFrag af[4];
            BFrag bf[2];
            #pragma unroll
            for (int mf = 0; mf < 4; mf++)
                wmma::load_matrix_sync(af[mf], As + (wm * 64 + mf * 16) * A_STRH + kk * 16, A_STRH);
            #pragma unroll
            for (int nf = 0; nf < 2; nf++)
                wmma::load_matrix_sync(bf[nf], Bs + (kk * 16) * B_STRH + wn * 32 + nf * 16, B_STRH);
            #pragma unroll
            for (int mf = 0; mf < 4; mf++)
                #pragma unroll
                for (int nf = 0; nf < 2; nf++)
                    wmma::mma_sync(acc[mf][nf], af[mf], bf[nf], acc[mf][nf]);
        }
        __syncthreads();   // stage t fully consumed before next iter's refill of this slot region? (kept for slot t%3 reuse at t+3)
    }

    #pragma unroll
    for (int mf = 0; mf < 4; mf++) {
        int gr = row0 + wm * 64 + mf * 16;
        #pragma unroll
        for (int nf = 0; nf < 2; nf++) {
            int gc = col0 + wn * 32 + nf * 16;
            if (gc + 16 <= N)
                wmma::store_matrix_sync(C + (size_t)gr * ldc + gc, acc[mf][nf], ldc,
                                        wmma::mem_row_major);
        }
    }
}

// ---------------- fused RMSNorm: grid.y 0 -> q_a, 1 -> ckv ----------------
__global__ __launch_bounds__(256)
void rms_fused_kernel(const float* __restrict__ qa, const float* __restrict__ wq,
                      const float* __restrict__ ckv, const float* __restrict__ wkv,
                      const float* __restrict__ cosT, const float* __restrict__ sinT,
                      const int* __restrict__ pos,
                      __half* __restrict__ qn, __half* __restrict__ cnorm,
                      float* __restrict__ kpe, float* __restrict__ cache)
{
    const int s = blockIdx.x;
    const int tid = threadIdx.x;
    __shared__ float sred[256];

    if (blockIdx.y == 0) {
        const float* x = qa + (size_t)s * QL_;
        __half*      y = qn + (size_t)s * QL_;
        float v[6];
        float local = 0.f;
        #pragma unroll
        for (int i = 0; i < 6; i++) { int c = tid + i * 256; v[i] = x[c]; local += v[i] * v[i]; }
        sred[tid] = local; __syncthreads();
        for (int st = 128; st > 0; st >>= 1) {
            if (tid < st) sred[tid] += sred[tid + st];
            __syncthreads();
        }
        float scale = rsqrtf(sred[0] / (float)QL_ + EPS_);
        #pragma unroll
        for (int i = 0; i < 6; i++) { int c = tid + i * 256; y[c] = __float2half(v[i] * scale * wq[c]); }
    } else {
        const float* x = ckv + (size_t)s * CKV_W;
        float v[2];
        float local = 0.f;
        #pragma unroll
        for (int i = 0; i < 2; i++) { int c = tid + i * 256; v[i] = x[c]; local += v[i] * v[i]; }
        sred[tid] = local; __syncthreads();
        for (int st = 128; st > 0; st >>= 1) {
            if (tid < st) sred[tid] += sred[tid + st];
            __syncthreads();
        }
        float scale = rsqrtf(sred[0] / (float)KVL_ + EPS_);
        #pragma unroll
        for (int i = 0; i < 2; i++) {
            int c = tid + i * 256;
            float y = v[i] * scale * wkv[c];
            cnorm[(size_t)s * KVL_ + c] = __float2half(y);
            cache[(size_t)s * CKV_W + c] = y;
        }
        if (tid < D_ROPE) {
            int p = pos[s];
            const float* cr = cosT + (size_t)p * D_ROPE;
            const float* sr = sinT + (size_t)p * D_ROPE;
            const float* t  = x + KVL_;
            int i = tid;
            float val;
            if (i < 32) val = t[2 * i] * cr[i] - t[2 * i + 1] * sr[i];
            else { int i2 = i - 32; val = t[2 * i2 + 1] * cr[i] + t[2 * i2] * sr[i]; }
            kpe[(size_t)s * D_ROPE + i] = val;
            cache[(size_t)s * CKV_W + KVL_ + i] = val;
        }
    }
}

// ---------------- fused assemble Q/K (perm16) + V transpose ----------------
// grid (S_/64, H_), 256 threads
__global__ __launch_bounds__(256)
void assemble_fused_kernel(const float* __restrict__ q, const float* __restrict__ kv,
                           const float* __restrict__ kpe,
                           const float* __restrict__ cosT, const float* __restrict__ sinT,
                           const int* __restrict__ pos,
                           __half* __restrict__ Q, __half* __restrict__ K,
                           __half* __restrict__ V)
{
    const int s0 = blockIdx.x * 64;
    const int h  = blockIdx.y;
    const int tid = threadIdx.x;

    // ---- assemble Q/K: 64 rows x 192 dims ----
    #pragma unroll
    for (int it = 0; it < 48; it++) {
        int idx = it * 256 + tid;
        int sl = idx / QHEAD, d = idx % QHEAD;
        int s = s0 + sl;
        const float* qrow  = q  + (size_t)s * QDIM  + h * QHEAD;
        const float* kvrow = kv + (size_t)s * KVDIM + h * (D_NOPE + D_V);
        const size_t off = ((size_t)h * S_ + s) * QHEAD;

        float qv;
        if (d < D_NOPE) qv = qrow[d];
        else {
            int p = pos[s];
            const float* cr = cosT + (size_t)p * D_ROPE;
            const float* sr = sinT + (size_t)p * D_ROPE;
            const float* t  = qrow + D_NOPE;
            int i = d - D_NOPE;
            if (i < 32) qv = t[2 * i] * cr[i] - t[2 * i + 1] * sr[i];
            else { int i2 = i - 32; qv = t[2 * i2 + 1] * cr[i] + t[2 * i2] * sr[i]; }
        }
        float kvv = (d < D_NOPE) ? kvrow[d] : kpe[(size_t)s * D_ROPE + (d - D_NOPE)];
        int pd = perm16(d);
        Q[off + pd] = __float2half(qv);
        K[off + pd] = __float2half(kvv);
    }

    // ---- V transpose via smem ----
    __shared__ float vt[64 * 132];
    #pragma unroll
    for (int i = 0; i < 32; i++) {
        int idx = i * 256 + tid;
        int sl = idx >> 7, d = idx & 127;
        vt[sl * 132 + d] = kv[(size_t)(s0 + sl) * KVDIM + h * (D_NOPE + D_V) + D_NOPE + d];
    }
    __syncthreads();
    #pragma unroll
    for (int i = 0; i < 32; i++) {
        int idx = i * 256 + tid;
        int d = idx >> 6, sl = idx & 63;
        V[((size_t)h * D_V + d) * S_ + s0 + perm16(sl)] = __float2half(vt[sl * 132 + d]);
    }
}

// ---------------- fused flash attention (fp16) ----------------
#define QS_STR 200
#define KS_STR 200
#define VS_STR 40
#define SF_STR 36
#define PH_STR 40
#define QS_OFF 0
#define KS_OFF 25600
#define KS_BYTES 12800
#define VS_OFF (KS_OFF + 2*KS_BYTES)
#define VS_BYTES 10240
#define SF_OFF (VS_OFF + 2*VS_BYTES)
#define PH_OFF (SF_OFF + 64*SF_STR*4)
#define M_OFF  (PH_OFF + 64*PH_STR*2)
#define L_OFF  (M_OFF + 256)
#define AL_OFF (L_OFF + 256)
#define FLASH_SMEM (AL_OFF + 256)

__global__ __launch_bounds__(256, 2)
void flash_kernel(const __half* __restrict__ Q, const __half* __restrict__ K,
                  const __half* __restrict__ V, __half* __restrict__ attn)
{
    const int qt = blockIdx.x;
    const int h  = blockIdx.y;
    const int q0 = qt * 64;
    const int nt = 2 * qt + 2;

    extern __shared__ char sm[];
    const uint32_t sb = smem_u32(sm);
    float* mP = reinterpret_cast<float*>(sm + M_OFF);
    float* lP = reinterpret_cast<float*>(sm + L_OFF);
    float* aP = reinterpret_cast<float*>(sm + AL_OFF);

    const int tid = threadIdx.x;
    const int wid = tid >> 5;
    const int lid = tid & 31;
    const int gl  = lid >> 2;
    const int tg  = lid & 3;
    const int wm  = wid >> 2;
    const int wn  = wid & 3;

    const __half* Qg = Q + ((size_t)h * S_ + q0) * QHEAD;
    const __half* Kg = K + (size_t)h * S_ * QHEAD;
    const __half* Vg = V + (size_t)h * D_V * S_;

    auto issueKV = [&](int t, int st) {
        const __half* kp = Kg + (size_t)t * 32 * QHEAD;
        uint32_t kd = sb + KS_OFF + st * KS_BYTES;
        #pragma unroll
        for (int i = 0; i < 3; i++) {
            int idx = i * 256 + tid;
            int r = idx / 24, c = idx % 24;
            cp16(kd + r * (KS_STR * 2) + c * 16, kp + (size_t)r * QHEAD + c * 8);
        }
        uint32_t vd = sb + VS_OFF + st * VS_BYTES;
        #pragma unroll
        for (int i = 0; i < 2; i++) {
            int idx = i * 256 + tid;
            int d = idx >> 2, c = idx & 3;
            cp16(vd + d * (VS_STR * 2) + c * 16, Vg + (size_t)d * S_ + t * 32 + c * 8);
        }
    };

    #pragma unroll
    for (int i = 0; i < 6; i++) {
        int idx = i * 256 + tid;
        int r = idx / 24, c = idx % 24;
        cp16(sb + QS_OFF + r * (QS_STR * 2) + c * 16, Qg + (size_t)r * QHEAD + c * 8);
    }
    issueKV(0, 0);
    cp_commit();

    if (tid < 64) { mP[tid] = -1e30f; lP[tid] = 0.f; }

    float oacc[2][4][4];
    #pragma unroll
    for (int a = 0; a < 2; a++)
        #pragma unroll
        for (int b = 0; b < 4; b++)
            #pragma unroll
            for (int c = 0; c < 4; c++) oacc[a][b][c] = 0.f;

    const char* QsB = sm + QS_OFF;
    char* SfB = sm + SF_OFF;
    char* PhB = sm + PH_OFF;

    for (int t = 0; t < nt; t++) {
        const int st = t & 1;
        if (t + 1 < nt) { issueKV(t + 1, st ^ 1); cp_commit(); cp_wait<1>(); }
        else            { cp_wait<0>(); }
        __syncthreads();

        const char* KsB = sm + KS_OFF + st * KS_BYTES;
        float sacc[2][4] = {{0.f,0.f,0.f,0.f},{0.f,0.f,0.f,0.f}};
        const int bRow = wn * 8 + gl;
        #pragma unroll 4
        for (int kk = 0; kk < 12; kk++) {
            uint2 bb = *reinterpret_cast<const uint2*>(
                KsB + (bRow * KS_STR + kk * 16 + 4 * tg) * 2);
            #pragma unroll
            for (int mf = 0; mf < 2; mf++) {
                int r0 = wm * 32 + mf * 16 + gl;
                uint2 lo = *reinterpret_cast<const uint2*>(
                    QsB + (r0 * QS_STR + kk * 16 + 4 * tg) * 2);
                uint2 hi = *reinterpret_cast<const uint2*>(
                    QsB + ((r0 + 8) * QS_STR + kk * 16 + 4 * tg) * 2);
                mma16(sacc[mf], lo.x, hi.x, lo.y, hi.y, bb.x, bb.y);
            }
        }
        #pragma unroll
        for (int mf = 0; mf < 2; mf++) {
            int r0 = wm * 32 + mf * 16 + gl;
            int c0 = wn * 8 + 2 * tg;
            *reinterpret_cast<float2*>(SfB + (r0 * SF_STR + c0) * 4) =
                make_float2(sacc[mf][0], sacc[mf][1]);
            *reinterpret_cast<float2*>(SfB + ((r0 + 8) * SF_STR + c0) * 4) =
                make_float2(sacc[mf][2], sacc[mf][3]);
        }
        __syncthreads();

        {
            const int row = tid >> 2;
            const int cb  = (tid & 3) * 8;
            float* srow = reinterpret_cast<float*>(SfB) + row * SF_STR + cb;
            __half* prow = reinterpret_cast<__half*>(PhB) + row * PH_STR;
            float4 v0 = *reinterpret_cast<float4*>(srow);
            float4 v1 = *reinterpret_cast<float4*>(srow + 4);
            float v[8] = {v0.x, v0.y, v0.z, v0.w, v1.x, v1.y, v1.z, v1.w};
            const int rg = q0 + row;
            const int key0 = t * 32 + cb;
            const bool msk = (t >= 2 * qt);
            float mx = -1e30f;
            #pragma unroll
            for (int j = 0; j < 8; j++) {
                float val = v[j] * SCALE_;
                if (msk && (key0 + j) > rg) val = -1e30f;
                v[j] = val;
                mx = fmaxf(mx, val);
            }
            mx = fmaxf(mx, __shfl_xor_sync(0xffffffffu, mx, 1));
            mx = fmaxf(mx, __shfl_xor_sync(0xffffffffu, mx, 2));
            float mold = mP[row];
            float mnew = fmaxf(mold, mx);
            float al = __expf(mold - mnew);
            float sum = 0.f;
            #pragma unroll
            for (int j = 0; j < 8; j++) {
                float p = __expf(v[j] - mnew);
                sum += p;
                prow[perm16(cb + j)] = __float2half(p);
            }
            sum += __shfl_xor_sync(0xffffffffu, sum, 1);
            sum += __shfl_xor_sync(0xffffffffu, sum, 2);
            if ((tid & 3) == 0) {
                mP[row] = mnew;
                lP[row] = lP[row] * al + sum;
                aP[row] = al;
            }
        }
        __syncthreads();

        const char* VsB = sm + VS_OFF + st * VS_BYTES;
        #pragma unroll
        for (int mf = 0; mf < 2; mf++) {
            int r0 = wm * 32 + mf * 16 + gl;
            float a0 = aP[r0], a8 = aP[r0 + 8];
            #pragma unroll
            for (int nf = 0; nf < 4; nf++) {
                oacc[mf][nf][0] *= a0; oacc[mf][nf][1] *= a0;
                oacc[mf][nf][2] *= a8; oacc[mf][nf][3] *= a8;
            }
        }
        #pragma unroll
        for (int kk = 0; kk < 2; kk++) {
            uint2 alo[2], ahi[2];
            #pragma unroll
            for (int mf = 0; mf < 2; mf++) {
                int r0 = wm * 32 + mf * 16 + gl;
                alo[mf] = *reinterpret_cast<const uint2*>(
                    PhB + (r0 * PH_STR + kk * 16 + 4 * tg) * 2);
                ahi[mf] = *reinterpret_cast<const uint2*>(
                    PhB + ((r0 + 8) * PH_STR + kk * 16 + 4 * tg) * 2);
            }
            #pragma unroll
            for (int nf = 0; nf < 4; nf++) {
                int nc = wn * 32 + nf * 8 + gl;
                uint2 bv = *reinterpret_cast<const uint2*>(
                    VsB + (nc * VS_STR + kk * 16 + 4 * tg) * 2);
                #pragma unroll
                for (int mf = 0; mf < 2; mf++)
                    mma16(oacc[mf][nf], alo[mf].x, ahi[mf].x, alo[mf].y, ahi[mf].y, bv.x, bv.y);
            }
        }
        __syncthreads();
    }

    #pragma unroll
    for (int mf = 0; mf < 2; mf++) {
        int r0 = wm * 32 + mf * 16 + gl;
        float inv0 = 1.f / lP[r0];
        float inv8 = 1.f / lP[r0 + 8];
        #pragma unroll
        for (int nf = 0; nf < 4; nf++) {
            int col = h * D_V + wn * 32 + nf * 8 + 2 * tg;
            __half2* o0 = reinterpret_cast<__half2*>(attn + (size_t)(q0 + r0) * (H_ * D_V) + col);
            __half2* o8 = reinterpret_cast<__half2*>(attn + (size_t)(q0 + r0 + 8) * (H_ * D_V) + col);
            *o0 = __floats2half2_rn(oacc[mf][nf][0] * inv0, oacc[mf][nf][1] * inv0);
            *o8 = __floats2half2_rn(oacc[mf][nf][2] * inv8, oacc[mf][nf][3] * inv8);
        }
    }
}

// ---------------- host launch ----------------
extern "C" void kernel_launch(void* const* d_in, const int* in_sizes, int n_in,
                              void* d_out, int out_size)
{
    const float* x       = (const float*)d_in[0];
    const int*   pos     = (const int*)  d_in[2];
    const float* cosT    = (const float*)d_in[3];
    const float* sinT    = (const float*)d_in[4];
    const float* q_a_w   = (const float*)d_in[5];
    const float* q_a_ln  = (const float*)d_in[6];
    const float* q_b_w   = (const float*)d_in[7];
    const float* kv_a_w  = (const float*)d_in[8];
    const float* kv_a_ln = (const float*)d_in[9];
    const float* kv_b_w  = (const float*)d_in[10];
    const float* o_w     = (const float*)d_in[11];
    float* out = (float*)d_out;
    float* out_cache = out + (size_t)S_ * HID_;

    __half *xc, *wqa, *wqb, *wkva, *wkvb, *wo, *qn, *cnorm, *Q, *K, *V, *attn;
    float *qa, *ckv, *kpe, *q, *kv;
    cudaGetSymbolAddress((void**)&xc,     g_x);
    cudaGetSymbolAddress((void**)&wqa,    g_wqa);
    cudaGetSymbolAddress((void**)&wqb,    g_wqb);
    cudaGetSymbolAddress((void**)&wkva,   g_wkva);
    cudaGetSymbolAddress((void**)&wkvb,   g_wkvb);
    cudaGetSymbolAddress((void**)&wo,     g_wo);
    cudaGetSymbolAddress((void**)&qa,     g_qa);
    cudaGetSymbolAddress((void**)&qn,     g_qn);
    cudaGetSymbolAddress((void**)&ckv,    g_ckv);
    cudaGetSymbolAddress((void**)&cnorm,  g_cnorm);
    cudaGetSymbolAddress((void**)&kpe,    g_kpe);
    cudaGetSymbolAddress((void**)&q,      g_q);
    cudaGetSymbolAddress((void**)&kv,     g_kv);
    cudaGetSymbolAddress((void**)&Q,      g_Q);
    cudaGetSymbolAddress((void**)&K,      g_K);
    cudaGetSymbolAddress((void**)&V,      g_V);
    cudaGetSymbolAddress((void**)&attn,   g_attn);

    cudaFuncSetAttribute(pgemm_kernel, cudaFuncAttributeMaxDynamicSharedMemorySize, SMEM_P);
    cudaFuncSetAttribute(flash_kernel, cudaFuncAttributeMaxDynamicSharedMemorySize, FLASH_SMEM);

    // prep: all conversions in 1 launch
    {
        int n0 = S_ * HID_ / 4, n1 = HID_ * QL_ / 4, n2 = QL_ * QDIM / 4,
            n3 = KVL_ * KVDIM / 4, n4 = H_ * D_V * HID_ / 4,
            n5 = HID_ * KVA_PAD / 4;
        int total = n0 + n1 + n2 + n3 + n4 + n5;
        conv_multi_kernel<<<(total + 255) / 256, 256>>>(
            (const float4*)x,      (__half2*)xc,   n0,
            (const float4*)q_a_w,  (__half2*)wqa,  n1,
            (const float4*)q_b_w,  (__half2*)wqb,  n2,
            (const float4*)kv_b_w, (__half2*)wkvb, n3,
            (const float4*)o_w,    (__half2*)wo,   n4,
            kv_a_w, wkva, n5);
    }

    dim3 blk5(512);

    // 1) fused: qa = x@q_a_w (6 tiles) ; ckv = x@kv_a_w (3 tiles, padded)
    pgemm_kernel<<<dim3(9, S_/128), blk5, SMEM_P>>>(
        xc, HID_, HID_, wqa, QL_, qa, QL_, QL_, 6,
        xc, HID_, HID_, wkva, KVA_PAD, ckv, CKV_W, CKV_W);
    // 2) fused RMSNorms
    rms_fused_kernel<<<dim3(S_, 2), 256>>>(qa, q_a_ln, ckv, kv_a_ln, cosT, sinT, pos,
                                           qn, cnorm, kpe, out_cache);
    // 3) fused: q = qn@q_b_w (12 tiles, K=1536) ; kv = cnorm@kv_b_w (16 tiles, K=512)
    pgemm_kernel<<<dim3(28, S_/128), blk5, SMEM_P>>>(
        qn, QL_, QL_, wqb, QDIM, q, QDIM, QDIM, 12,
        cnorm, KVL_, KVL_, wkvb, KVDIM, kv, KVDIM, KVDIM);
    // 4) fused assemble Q/K + V transpose
    assemble_fused_kernel<<<dim3(S_/64, H_), 256>>>(q, kv, kpe, cosT, sinT, pos, Q, K, V);
    // 5) fused flash attention
    flash_kernel<<<dim3(S_/64, H_), 256, FLASH_SMEM>>>(Q, K, V, attn);
    // 6) out = attn @ o_w
    pgemm_kernel<<<dim3(HID_/256, S_/128), blk5, SMEM_P>>>(
        attn, H_*D_V, H_*D_V, wo, HID_, out, HID_, HID_, HID_/256,
        nullptr, 0, 0, nullptr, 0, nullptr, 0, 0);
}